// round 4
// baseline (speedup 1.0000x reference)
#include <cuda_runtime.h>
#include <cuda_bf16.h>
#include <cstdint>

#define TT   2048
#define DIMK 1024
#define HIDN 128

typedef unsigned long long u64;
typedef unsigned int u32;

// ---------------- scratch (__device__ globals; no runtime alloc) ------------
__device__ float         g_z[TT * TT];      // z[s][b*256+2h]=eK*V, [..2h+1]=eK
__device__ __nv_bfloat16 g_Ah[TT * TT];     // exp(w) hi  [t][s] K-major
__device__ __nv_bfloat16 g_Al[TT * TT];     // exp(w) lo
__device__ __nv_bfloat16 g_Bh[TT * TT];     // zT hi [col][s] K-major
__device__ __nv_bfloat16 g_Bl[TT * TT];     // zT lo
__device__ __nv_bfloat16 g_xh[16384 * DIMK];  // x hi [m][k]
__device__ __nv_bfloat16 g_xl[16384 * DIMK];  // x lo
__device__ __nv_bfloat16 g_wth[256 * DIMK];   // W^T interleaved hi [n][k]
__device__ __nv_bfloat16 g_wtl[256 * DIMK];   // W^T interleaved lo

// ---------------- helpers ----------------------------------------------------
__device__ __forceinline__ u32 smem_u32(const void* p) {
    u32 a;
    asm("{ .reg .u64 t; cvta.to.shared.u64 t, %1; cvt.u32.u64 %0, t; }"
        : "=r"(a) : "l"(p));
    return a;
}
__device__ __forceinline__ void cp16(u32 s, const void* g) {
    asm volatile("cp.async.cg.shared.global [%0], [%1], 16;" :: "r"(s), "l"(g));
}
#define CP_COMMIT() asm volatile("cp.async.commit_group;" ::: "memory")
#define CP_WAIT2()  asm volatile("cp.async.wait_group 2;" ::: "memory")

__device__ __forceinline__ void ldsm4(u32 addr, u32& r0, u32& r1, u32& r2, u32& r3) {
    asm volatile("ldmatrix.sync.aligned.m8n8.x4.shared.b16 {%0,%1,%2,%3}, [%4];"
                 : "=r"(r0), "=r"(r1), "=r"(r2), "=r"(r3) : "r"(addr));
}
__device__ __forceinline__ void mma16816(float* d, u32 a0, u32 a1, u32 a2, u32 a3,
                                         u32 b0, u32 b1) {
    asm volatile(
        "mma.sync.aligned.m16n8k16.row.col.f32.bf16.bf16.f32 "
        "{%0,%1,%2,%3}, {%4,%5,%6,%7}, {%8,%9}, {%0,%1,%2,%3};"
        : "+f"(d[0]), "+f"(d[1]), "+f"(d[2]), "+f"(d[3])
        : "r"(a0), "r"(a1), "r"(a2), "r"(a3), "r"(b0), "r"(b1));
}
__device__ __forceinline__ void split_bf16(float v, unsigned short& h, unsigned short& l) {
    __nv_bfloat16 hb = __float2bfloat16(v);
    __nv_bfloat16 lb = __float2bfloat16(v - __bfloat162float(hb));
    h = __bfloat16_as_ushort(hb);
    l = __bfloat16_as_ushort(lb);
}

// ---------------- smem layout for the two TC GEMMs (identical) --------------
#define ROWB   80
#define A_ROWS 128
#define B_ROWS 256
#define MATA_B (A_ROWS * ROWB)              // 10240
#define MATB_B (B_ROWS * ROWB)              // 20480
#define OFF_AH 0
#define OFF_AL MATA_B
#define OFF_BH (2 * MATA_B)
#define OFF_BL (2 * MATA_B + MATB_B)
#define STAGEB (2 * MATA_B + 2 * MATB_B)    // 61440
#define SMEMTOT (3 * STAGEB)                // 184320

// generic stage loader: A rows from (pAh,pAl) stride strideA bytes,
// B rows from (pBh,pBl) stride strideB bytes; 512 threads.
__device__ __forceinline__ void load_stage(
    u32 dst, const char* pAh, const char* pAl, size_t strideA, int m0,
    const char* pBh, const char* pBl, size_t strideB, int n0,
    int chunk, int tid) {
    const size_t cb = (size_t)chunk * 64;
#pragma unroll
    for (int i = 0; i < 2; i++) {
        int idx = tid * 2 + i;          // 0..1023
        int mat = idx >> 9;
        int rr = (idx & 511) >> 2;
        int ko = idx & 3;
        const char* src = (mat ? pAl : pAh) + (size_t)(m0 + rr) * strideA + cb + (size_t)ko * 16;
        cp16(dst + (mat ? OFF_AL : OFF_AH) + (u32)rr * ROWB + (u32)ko * 16, src);
    }
#pragma unroll
    for (int i = 0; i < 4; i++) {
        int idx = tid * 4 + i;          // 0..2047
        int mat = idx >> 10;
        int rr = (idx & 1023) >> 2;
        int ko = idx & 3;
        const char* src = (mat ? pBl : pBh) + (size_t)(n0 + rr) * strideB + cb + (size_t)ko * 16;
        cp16(dst + (mat ? OFF_BL : OFF_BH) + (u32)rr * ROWB + (u32)ko * 16, src);
    }
}

// bf16x3 compute for one k=32 chunk (per warp, warp tile 64x32)
__device__ __forceinline__ void compute_chunk(u32 s0, u32 aoff, u32 boff,
                                              float (&acc)[4][4][4]) {
#pragma unroll
    for (int ks = 0; ks < 2; ks++) {
        const u32 ak = aoff + (u32)ks * 32;
        const u32 bko = boff + (u32)ks * 32;
        u32 Af[4][4], Bh[2][4], Bl[2][4];
#pragma unroll
        for (int mt = 0; mt < 4; mt++)
            ldsm4(s0 + OFF_AH + ak + (u32)mt * (16 * ROWB),
                  Af[mt][0], Af[mt][1], Af[mt][2], Af[mt][3]);
#pragma unroll
        for (int np = 0; np < 2; np++)
            ldsm4(s0 + OFF_BH + bko + (u32)np * (16 * ROWB),
                  Bh[np][0], Bh[np][1], Bh[np][2], Bh[np][3]);
#pragma unroll
        for (int np = 0; np < 2; np++)
            ldsm4(s0 + OFF_BL + bko + (u32)np * (16 * ROWB),
                  Bl[np][0], Bl[np][1], Bl[np][2], Bl[np][3]);
        // pass 1: Ah*Bh
#pragma unroll
        for (int mt = 0; mt < 4; mt++)
#pragma unroll
            for (int nt = 0; nt < 4; nt++)
                mma16816(acc[mt][nt], Af[mt][0], Af[mt][1], Af[mt][2], Af[mt][3],
                         Bh[nt >> 1][(nt & 1) * 2], Bh[nt >> 1][(nt & 1) * 2 + 1]);
        // pass 2: Ah*Bl
#pragma unroll
        for (int mt = 0; mt < 4; mt++)
#pragma unroll
            for (int nt = 0; nt < 4; nt++)
                mma16816(acc[mt][nt], Af[mt][0], Af[mt][1], Af[mt][2], Af[mt][3],
                         Bl[nt >> 1][(nt & 1) * 2], Bl[nt >> 1][(nt & 1) * 2 + 1]);
        // pass 3: Al*Bh (reload A regs with lo)
#pragma unroll
        for (int mt = 0; mt < 4; mt++)
            ldsm4(s0 + OFF_AL + ak + (u32)mt * (16 * ROWB),
                  Af[mt][0], Af[mt][1], Af[mt][2], Af[mt][3]);
#pragma unroll
        for (int mt = 0; mt < 4; mt++)
#pragma unroll
            for (int nt = 0; nt < 4; nt++)
                mma16816(acc[mt][nt], Af[mt][0], Af[mt][1], Af[mt][2], Af[mt][3],
                         Bh[nt >> 1][(nt & 1) * 2], Bh[nt >> 1][(nt & 1) * 2 + 1]);
    }
}

// ---------------- Kernel: exp(w) -> A hi/lo ----------------------------------
__global__ void k_expw2(const float* __restrict__ w) {
    int i = blockIdx.x * blockDim.x + threadIdx.x;
    float4 v = ((const float4*)w)[i];
    float e[4] = {__expf(v.x), __expf(v.y), __expf(v.z), __expf(v.w)};
    ushort4 H, L;
    unsigned short* hp = &H.x;
    unsigned short* lp = &L.x;
#pragma unroll
    for (int q = 0; q < 4; q++) split_bf16(e[q], hp[q], lp[q]);
    ((ushort4*)g_Ah)[i] = H;
    ((ushort4*)g_Al)[i] = L;
}

// ---------------- Kernel: x -> bf16 hi/lo ------------------------------------
__global__ void k_xsplit(const float* __restrict__ x) {
    int i = blockIdx.x * blockDim.x + threadIdx.x;  // float4 index, 4M total
    float4 v = ((const float4*)x)[i];
    float e[4] = {v.x, v.y, v.z, v.w};
    ushort4 H, L;
    unsigned short* hp = &H.x;
    unsigned short* lp = &L.x;
#pragma unroll
    for (int q = 0; q < 4; q++) split_bf16(e[q], hp[q], lp[q]);
    ((ushort4*)g_xh)[i] = H;
    ((ushort4*)g_xl)[i] = L;
}

// ---------------- Kernel: W^T interleave + split ------------------------------
// g_wth[n][k]: n=2h -> wk[k][h], n=2h+1 -> wv[k][h]
__global__ void k_wsplit(const float* __restrict__ wk, const float* __restrict__ wv) {
    __shared__ float tK[32][33], tV[32][33];
    const int bs = blockIdx.x << 5;  // k block
    const int bh = blockIdx.y << 5;  // h block
    const int tx = threadIdx.x, ty = threadIdx.y;
#pragma unroll
    for (int i = 0; i < 32; i += 8) {
        tK[ty + i][tx] = wk[(bs + ty + i) * HIDN + bh + tx];
        tV[ty + i][tx] = wv[(bs + ty + i) * HIDN + bh + tx];
    }
    __syncthreads();
#pragma unroll
    for (int i = 0; i < 32; i += 8) {
        int hl = ty + i;
        unsigned short h, l;
        split_bf16(tK[tx][hl], h, l);
        size_t oK = (size_t)(2 * (bh + hl)) * DIMK + bs + tx;
        g_wth[oK] = __ushort_as_bfloat16(h);
        g_wtl[oK] = __ushort_as_bfloat16(l);
        split_bf16(tV[tx][hl], h, l);
        g_wth[oK + DIMK] = __ushort_as_bfloat16(h);
        g_wtl[oK + DIMK] = __ushort_as_bfloat16(l);
    }
}

// ---------------- Kernel: projection GEMM (HMMA bf16x3) + exp epilogue ------
#define NCH_P (DIMK / 32)   // 32
__global__ __launch_bounds__(512, 1) void k_projTC(
    const float* __restrict__ bk, const float* __restrict__ bv) {
    extern __shared__ char smem[];
    const u32 sb = smem_u32(smem);
    const int tid = threadIdx.x;
    const int wid = tid >> 5, lane = tid & 31;
    const int m0 = blockIdx.x << 7;     // 0..16256
    const int warp_m = wid >> 3, warp_n = wid & 7;
    const int m_base = warp_m * 64, n_base = warp_n * 32;

    float acc[4][4][4];
#pragma unroll
    for (int i = 0; i < 4; i++)
#pragma unroll
        for (int j = 0; j < 4; j++)
#pragma unroll
            for (int q = 0; q < 4; q++) acc[i][j][q] = 0.0f;

    const u32 aoff = (u32)(m_base + (lane & 15)) * ROWB + (u32)(lane >> 4) * 16;
    const u32 boff = (u32)(n_base + (lane & 7) + ((lane >> 4) << 3)) * ROWB +
                     (u32)((lane >> 3) & 1) * 16;

    load_stage(sb + 0 * STAGEB, (const char*)g_xh, (const char*)g_xl, 2048, m0,
               (const char*)g_wth, (const char*)g_wtl, 2048, 0, 0, tid); CP_COMMIT();
    load_stage(sb + 1 * STAGEB, (const char*)g_xh, (const char*)g_xl, 2048, m0,
               (const char*)g_wth, (const char*)g_wtl, 2048, 0, 1, tid); CP_COMMIT();
    load_stage(sb + 2 * STAGEB, (const char*)g_xh, (const char*)g_xl, 2048, m0,
               (const char*)g_wth, (const char*)g_wtl, 2048, 0, 2, tid); CP_COMMIT();

#pragma unroll 1
    for (int c = 0; c < NCH_P; c++) {
        CP_WAIT2();
        __syncthreads();
        compute_chunk(sb + (u32)(c % 3) * STAGEB, aoff, boff, acc);
        __syncthreads();
        if (c + 3 < NCH_P) {
            load_stage(sb + (u32)((c + 3) % 3) * STAGEB,
                       (const char*)g_xh, (const char*)g_xl, 2048, m0,
                       (const char*)g_wth, (const char*)g_wtl, 2048, 0, c + 3, tid);
            CP_COMMIT();
        }
    }

    // epilogue: bias + exp, write z fp32
    const int b = (m0 + m_base) >> 11;
#pragma unroll
    for (int mt = 0; mt < 4; mt++) {
        const int m = m0 + m_base + mt * 16 + (lane >> 2);
        const int s = m & 2047;
#pragma unroll
        for (int nt = 0; nt < 4; nt++) {
            const int c0 = n_base + nt * 8 + 2 * (lane & 3);
            const int h = c0 >> 1;
            const float bkh = bk[h], bvh = bv[h];
            float ek0 = __expf(acc[mt][nt][0] + bkh);
            float v0 = acc[mt][nt][1] + bvh;
            float ek1 = __expf(acc[mt][nt][2] + bkh);
            float v1 = acc[mt][nt][3] + bvh;
            float* d0 = g_z + (size_t)s * TT + b * 256 + c0;
            *(float2*)d0 = make_float2(ek0 * v0, ek0);
            *(float2*)(d0 + 8 * TT) = make_float2(ek1 * v1, ek1);
        }
    }
}

// ---------------- Kernel: transpose+split z -> B hi/lo ----------------------
__global__ void k_zT() {
    __shared__ float tile[32][33];
    const int bc = blockIdx.x << 5;
    const int bs = blockIdx.y << 5;
    const int tx = threadIdx.x, ty = threadIdx.y;
#pragma unroll
    for (int i = 0; i < 32; i += 8)
        tile[ty + i][tx] = g_z[(size_t)(bs + ty + i) * TT + bc + tx];
    __syncthreads();
#pragma unroll
    for (int i = 0; i < 32; i += 8) {
        unsigned short h, l;
        split_bf16(tile[tx][ty + i], h, l);
        size_t o = (size_t)(bc + ty + i) * TT + bs + tx;
        g_Bh[o] = __ushort_as_bfloat16(h);
        g_Bl[o] = __ushort_as_bfloat16(l);
    }
}

// ---------------- Kernel: main GEMM (HMMA bf16x3) + num/den epilogue --------
#define NCH_M (TT / 32)   // 64
__global__ __launch_bounds__(512, 1) void k_mainTC(float* __restrict__ out) {
    extern __shared__ char smem[];
    const u32 sb = smem_u32(smem);
    const int tid = threadIdx.x;
    const int wid = tid >> 5, lane = tid & 31;
    const int m0 = blockIdx.x << 7;   // t tile (16)
    const int n0 = blockIdx.y << 8;   // col tile (8 x 256)
    const int warp_m = wid >> 3, warp_n = wid & 7;
    const int m_base = warp_m * 64, n_base = warp_n * 32;

    float acc[4][4][4];
#pragma unroll
    for (int i = 0; i < 4; i++)
#pragma unroll
        for (int j = 0; j < 4; j++)
#pragma unroll
            for (int q = 0; q < 4; q++) acc[i][j][q] = 0.0f;

    const u32 aoff = (u32)(m_base + (lane & 15)) * ROWB + (u32)(lane >> 4) * 16;
    const u32 boff = (u32)(n_base + (lane & 7) + ((lane >> 4) << 3)) * ROWB +
                     (u32)((lane >> 3) & 1) * 16;

    load_stage(sb + 0 * STAGEB, (const char*)g_Ah, (const char*)g_Al, 4096, m0,
               (const char*)g_Bh, (const char*)g_Bl, 4096, n0, 0, tid); CP_COMMIT();
    load_stage(sb + 1 * STAGEB, (const char*)g_Ah, (const char*)g_Al, 4096, m0,
               (const char*)g_Bh, (const char*)g_Bl, 4096, n0, 1, tid); CP_COMMIT();
    load_stage(sb + 2 * STAGEB, (const char*)g_Ah, (const char*)g_Al, 4096, m0,
               (const char*)g_Bh, (const char*)g_Bl, 4096, n0, 2, tid); CP_COMMIT();

#pragma unroll 1
    for (int c = 0; c < NCH_M; c++) {
        CP_WAIT2();
        __syncthreads();
        compute_chunk(sb + (u32)(c % 3) * STAGEB, aoff, boff, acc);
        __syncthreads();
        if (c + 3 < NCH_M) {
            load_stage(sb + (u32)((c + 3) % 3) * STAGEB,
                       (const char*)g_Ah, (const char*)g_Al, 4096, m0,
                       (const char*)g_Bh, (const char*)g_Bl, 4096, n0, c + 3, tid);
            CP_COMMIT();
        }
    }

    // epilogue: out = num/den
    const int b = n0 >> 8;
#pragma unroll
    for (int mt = 0; mt < 4; mt++) {
        const int t0 = m0 + m_base + mt * 16 + (lane >> 2);
#pragma unroll
        for (int nt = 0; nt < 4; nt++) {
            const int gcol = n_base + nt * 8 + 2 * (lane & 3);
            const int h = gcol >> 1;
            float* o0 = out + ((size_t)(b * TT + t0)) * HIDN + h;
            o0[0] = __fdividef(acc[mt][nt][0], acc[mt][nt][1]);
            o0[8 * HIDN] = __fdividef(acc[mt][nt][2], acc[mt][nt][3]);
        }
    }
}

// ---------------- launch ----------------
extern "C" void kernel_launch(void* const* d_in, const int* in_sizes, int n_in,
                              void* d_out, int out_size) {
    const float* x  = (const float*)d_in[0];
    const float* wk = (const float*)d_in[1];
    const float* bk = (const float*)d_in[2];
    const float* wv = (const float*)d_in[3];
    const float* bv = (const float*)d_in[4];
    const float* w  = (const float*)d_in[5];
    float* out = (float*)d_out;

    cudaFuncSetAttribute(k_mainTC, cudaFuncAttributeMaxDynamicSharedMemorySize, SMEMTOT);
    cudaFuncSetAttribute(k_projTC, cudaFuncAttributeMaxDynamicSharedMemorySize, SMEMTOT);

    k_expw2<<<4096, 256>>>(w);                       // exp(w) -> Ah/Al
    k_xsplit<<<16384, 256>>>(x);                     // x -> xh/xl
    k_wsplit<<<dim3(32, 4), dim3(32, 8)>>>(wk, wv);  // W^T interleave/split
    k_projTC<<<128, 512, SMEMTOT>>>(bk, bv);         // z (fp32)
    k_zT<<<dim3(64, 64), dim3(32, 8)>>>();           // z -> Bh/Bl (transposed)
    k_mainTC<<<dim3(16, 8), 512, SMEMTOT>>>(out);    // out
}

// round 5
// speedup vs baseline: 1.3966x; 1.3966x over previous
#include <cuda_runtime.h>
#include <cuda_bf16.h>
#include <cstdint>

#define TT   2048
#define DIMK 1024
#define HIDN 128

typedef unsigned long long u64;
typedef unsigned int u32;

// ---------------- scratch (__device__ globals; no runtime alloc) ------------
__device__ float         g_z[TT * TT];
__device__ __nv_bfloat16 g_Ah[TT * TT];
__device__ __nv_bfloat16 g_Al[TT * TT];
__device__ __nv_bfloat16 g_Bh[TT * TT];
__device__ __nv_bfloat16 g_Bl[TT * TT];
__device__ __nv_bfloat16 g_xh[16384 * DIMK];
__device__ __nv_bfloat16 g_xl[16384 * DIMK];
__device__ __nv_bfloat16 g_wth[256 * DIMK];
__device__ __nv_bfloat16 g_wtl[256 * DIMK];

// ---------------- helpers ----------------------------------------------------
__device__ __forceinline__ u32 smem_u32(const void* p) {
    u32 a;
    asm("{ .reg .u64 t; cvta.to.shared.u64 t, %1; cvt.u32.u64 %0, t; }"
        : "=r"(a) : "l"(p));
    return a;
}
__device__ __forceinline__ void cp16(u32 s, const void* g) {
    asm volatile("cp.async.cg.shared.global [%0], [%1], 16;" :: "r"(s), "l"(g));
}
#define CP_COMMIT() asm volatile("cp.async.commit_group;" ::: "memory")
#define CP_WAIT1()  asm volatile("cp.async.wait_group 1;" ::: "memory")

__device__ __forceinline__ void ldsm4(u32 addr, u32& r0, u32& r1, u32& r2, u32& r3) {
    asm volatile("ldmatrix.sync.aligned.m8n8.x4.shared.b16 {%0,%1,%2,%3}, [%4];"
                 : "=r"(r0), "=r"(r1), "=r"(r2), "=r"(r3) : "r"(addr));
}
__device__ __forceinline__ void mma16816(float* d, u32 a0, u32 a1, u32 a2, u32 a3,
                                         u32 b0, u32 b1) {
    asm volatile(
        "mma.sync.aligned.m16n8k16.row.col.f32.bf16.bf16.f32 "
        "{%0,%1,%2,%3}, {%4,%5,%6,%7}, {%8,%9}, {%0,%1,%2,%3};"
        : "+f"(d[0]), "+f"(d[1]), "+f"(d[2]), "+f"(d[3])
        : "r"(a0), "r"(a1), "r"(a2), "r"(a3), "r"(b0), "r"(b1));
}
__device__ __forceinline__ void split_bf16(float v, unsigned short& h, unsigned short& l) {
    __nv_bfloat16 hb = __float2bfloat16(v);
    __nv_bfloat16 lb = __float2bfloat16(v - __bfloat162float(hb));
    h = __bfloat16_as_ushort(hb);
    l = __bfloat16_as_ushort(lb);
}

// ---------------- smem layout (identical for both GEMMs) --------------------
// 128x128 CTA tile, k-chunk 32. 4 operand mats (Ah, Al, Bh, Bl), 128 rows x 64B.
#define ROWB   80
#define MAT_B  (128 * ROWB)          // 10240
#define OFF_AH 0
#define OFF_AL MAT_B
#define OFF_BH (2 * MAT_B)
#define OFF_BL (3 * MAT_B)
#define STAGEB (4 * MAT_B)           // 40960
#define SMEMTOT (2 * STAGEB)         // 81920 -> 2 CTAs/SM

// 256-thread stage loader: 2048 cp16 total -> 8 per thread.
__device__ __forceinline__ void load_stage(
    u32 dst, const char* pAh, const char* pAl, size_t strideA, int m0,
    const char* pBh, const char* pBl, size_t strideB, int n0,
    int chunk, int tid) {
    const size_t cb = (size_t)chunk * 64;
#pragma unroll
    for (int i = 0; i < 4; i++) {
        int idx = tid * 4 + i;             // 0..1023 (A)
        int mat = idx >> 9;
        int rr = (idx & 511) >> 2;
        int ko = idx & 3;
        const char* src = (mat ? pAl : pAh) + (size_t)(m0 + rr) * strideA + cb + (size_t)ko * 16;
        cp16(dst + (mat ? OFF_AL : OFF_AH) + (u32)rr * ROWB + (u32)ko * 16, src);
    }
#pragma unroll
    for (int i = 0; i < 4; i++) {
        int idx = tid * 4 + i;             // 0..1023 (B)
        int mat = idx >> 9;
        int rr = (idx & 511) >> 2;
        int ko = idx & 3;
        const char* src = (mat ? pBl : pBh) + (size_t)(n0 + rr) * strideB + cb + (size_t)ko * 16;
        cp16(dst + (mat ? OFF_BL : OFF_BH) + (u32)rr * ROWB + (u32)ko * 16, src);
    }
}

// bf16x3 compute for one k=32 chunk (warp tile 64x32)
__device__ __forceinline__ void compute_chunk(u32 s0, u32 aoff, u32 boff,
                                              float (&acc)[4][4][4]) {
#pragma unroll
    for (int ks = 0; ks < 2; ks++) {
        const u32 ak = aoff + (u32)ks * 32;
        const u32 bko = boff + (u32)ks * 32;
        u32 Af[4][4], Bh[2][4], Bl[2][4];
#pragma unroll
        for (int mt = 0; mt < 4; mt++)
            ldsm4(s0 + OFF_AH + ak + (u32)mt * (16 * ROWB),
                  Af[mt][0], Af[mt][1], Af[mt][2], Af[mt][3]);
#pragma unroll
        for (int np = 0; np < 2; np++)
            ldsm4(s0 + OFF_BH + bko + (u32)np * (16 * ROWB),
                  Bh[np][0], Bh[np][1], Bh[np][2], Bh[np][3]);
#pragma unroll
        for (int np = 0; np < 2; np++)
            ldsm4(s0 + OFF_BL + bko + (u32)np * (16 * ROWB),
                  Bl[np][0], Bl[np][1], Bl[np][2], Bl[np][3]);
#pragma unroll
        for (int mt = 0; mt < 4; mt++)
#pragma unroll
            for (int nt = 0; nt < 4; nt++)
                mma16816(acc[mt][nt], Af[mt][0], Af[mt][1], Af[mt][2], Af[mt][3],
                         Bh[nt >> 1][(nt & 1) * 2], Bh[nt >> 1][(nt & 1) * 2 + 1]);
#pragma unroll
        for (int mt = 0; mt < 4; mt++)
#pragma unroll
            for (int nt = 0; nt < 4; nt++)
                mma16816(acc[mt][nt], Af[mt][0], Af[mt][1], Af[mt][2], Af[mt][3],
                         Bl[nt >> 1][(nt & 1) * 2], Bl[nt >> 1][(nt & 1) * 2 + 1]);
#pragma unroll
        for (int mt = 0; mt < 4; mt++)
            ldsm4(s0 + OFF_AL + ak + (u32)mt * (16 * ROWB),
                  Af[mt][0], Af[mt][1], Af[mt][2], Af[mt][3]);
#pragma unroll
        for (int mt = 0; mt < 4; mt++)
#pragma unroll
            for (int nt = 0; nt < 4; nt++)
                mma16816(acc[mt][nt], Af[mt][0], Af[mt][1], Af[mt][2], Af[mt][3],
                         Bh[nt >> 1][(nt & 1) * 2], Bh[nt >> 1][(nt & 1) * 2 + 1]);
    }
}

// ---------------- elementwise prep kernels -----------------------------------
__global__ void k_expw2(const float* __restrict__ w) {
    int i = blockIdx.x * blockDim.x + threadIdx.x;
    float4 v = ((const float4*)w)[i];
    float e[4] = {__expf(v.x), __expf(v.y), __expf(v.z), __expf(v.w)};
    ushort4 H, L;
    unsigned short* hp = &H.x;
    unsigned short* lp = &L.x;
#pragma unroll
    for (int q = 0; q < 4; q++) split_bf16(e[q], hp[q], lp[q]);
    ((ushort4*)g_Ah)[i] = H;
    ((ushort4*)g_Al)[i] = L;
}

__global__ void k_xsplit(const float* __restrict__ x) {
    int i = blockIdx.x * blockDim.x + threadIdx.x;
    float4 v = ((const float4*)x)[i];
    float e[4] = {v.x, v.y, v.z, v.w};
    ushort4 H, L;
    unsigned short* hp = &H.x;
    unsigned short* lp = &L.x;
#pragma unroll
    for (int q = 0; q < 4; q++) split_bf16(e[q], hp[q], lp[q]);
    ((ushort4*)g_xh)[i] = H;
    ((ushort4*)g_xl)[i] = L;
}

__global__ void k_wsplit(const float* __restrict__ wk, const float* __restrict__ wv) {
    __shared__ float tK[32][33], tV[32][33];
    const int bs = blockIdx.x << 5;
    const int bh = blockIdx.y << 5;
    const int tx = threadIdx.x, ty = threadIdx.y;
#pragma unroll
    for (int i = 0; i < 32; i += 8) {
        tK[ty + i][tx] = wk[(bs + ty + i) * HIDN + bh + tx];
        tV[ty + i][tx] = wv[(bs + ty + i) * HIDN + bh + tx];
    }
    __syncthreads();
#pragma unroll
    for (int i = 0; i < 32; i += 8) {
        int hl = ty + i;
        unsigned short h, l;
        split_bf16(tK[tx][hl], h, l);
        size_t oK = (size_t)(2 * (bh + hl)) * DIMK + bs + tx;
        g_wth[oK] = __ushort_as_bfloat16(h);
        g_wtl[oK] = __ushort_as_bfloat16(l);
        split_bf16(tV[tx][hl], h, l);
        g_wth[oK + DIMK] = __ushort_as_bfloat16(h);
        g_wtl[oK + DIMK] = __ushort_as_bfloat16(l);
    }
}

__global__ void k_zT() {
    __shared__ float tile[32][33];
    const int bc = blockIdx.x << 5;
    const int bs = blockIdx.y << 5;
    const int tx = threadIdx.x, ty = threadIdx.y;
#pragma unroll
    for (int i = 0; i < 32; i += 8)
        tile[ty + i][tx] = g_z[(size_t)(bs + ty + i) * TT + bc + tx];
    __syncthreads();
#pragma unroll
    for (int i = 0; i < 32; i += 8) {
        unsigned short h, l;
        split_bf16(tile[tx][ty + i], h, l);
        size_t o = (size_t)(bc + ty + i) * TT + bs + tx;
        g_Bh[o] = __ushort_as_bfloat16(h);
        g_Bl[o] = __ushort_as_bfloat16(l);
    }
}

// ---------------- GEMM kernels (256 thr, 8 warps, 2 CTAs/SM) ----------------
#define NCH_P (DIMK / 32)   // 32
__global__ __launch_bounds__(256, 2) void k_projTC(
    const float* __restrict__ bk, const float* __restrict__ bv) {
    extern __shared__ char smem[];
    const u32 sb = smem_u32(smem);
    const int tid = threadIdx.x;
    const int wid = tid >> 5, lane = tid & 31;
    const int m0 = blockIdx.x << 7;     // 128 blocks
    const int n0 = blockIdx.y << 7;     // 2 blocks
    const int warp_m = wid >> 2, warp_n = wid & 3;
    const int m_base = warp_m * 64, n_base = warp_n * 32;

    float acc[4][4][4];
#pragma unroll
    for (int i = 0; i < 4; i++)
#pragma unroll
        for (int j = 0; j < 4; j++)
#pragma unroll
            for (int q = 0; q < 4; q++) acc[i][j][q] = 0.0f;

    const u32 aoff = (u32)(m_base + (lane & 15)) * ROWB + (u32)(lane >> 4) * 16;
    const u32 boff = (u32)(n_base + (lane & 7) + ((lane >> 4) << 3)) * ROWB +
                     (u32)((lane >> 3) & 1) * 16;

    load_stage(sb + 0 * STAGEB, (const char*)g_xh, (const char*)g_xl, 2048, m0,
               (const char*)g_wth, (const char*)g_wtl, 2048, n0, 0, tid); CP_COMMIT();
    load_stage(sb + 1 * STAGEB, (const char*)g_xh, (const char*)g_xl, 2048, m0,
               (const char*)g_wth, (const char*)g_wtl, 2048, n0, 1, tid); CP_COMMIT();

#pragma unroll 1
    for (int c = 0; c < NCH_P; c++) {
        CP_WAIT1();
        __syncthreads();
        compute_chunk(sb + (u32)(c & 1) * STAGEB, aoff, boff, acc);
        __syncthreads();
        if (c + 2 < NCH_P) {
            load_stage(sb + (u32)(c & 1) * STAGEB,
                       (const char*)g_xh, (const char*)g_xl, 2048, m0,
                       (const char*)g_wth, (const char*)g_wtl, 2048, n0, c + 2, tid);
            CP_COMMIT();
        }
    }

    const int b = m0 >> 11;
#pragma unroll
    for (int mt = 0; mt < 4; mt++) {
        const int m = m0 + m_base + mt * 16 + (lane >> 2);
        const int s = m & 2047;
#pragma unroll
        for (int nt = 0; nt < 4; nt++) {
            const int c0 = n0 + n_base + nt * 8 + 2 * (lane & 3);
            const int h = c0 >> 1;
            const float bkh = bk[h], bvh = bv[h];
            float ek0 = __expf(acc[mt][nt][0] + bkh);
            float v0 = acc[mt][nt][1] + bvh;
            float ek1 = __expf(acc[mt][nt][2] + bkh);
            float v1 = acc[mt][nt][3] + bvh;
            float* d0 = g_z + (size_t)s * TT + b * 256 + c0;
            *(float2*)d0 = make_float2(ek0 * v0, ek0);
            *(float2*)(d0 + 8 * TT) = make_float2(ek1 * v1, ek1);
        }
    }
}

#define NCH_M (TT / 32)   // 64
__global__ __launch_bounds__(256, 2) void k_mainTC(float* __restrict__ out) {
    extern __shared__ char smem[];
    const u32 sb = smem_u32(smem);
    const int tid = threadIdx.x;
    const int wid = tid >> 5, lane = tid & 31;
    const int m0 = blockIdx.x << 7;   // 16 t-tiles
    const int n0 = blockIdx.y << 7;   // 16 col-tiles
    const int warp_m = wid >> 2, warp_n = wid & 3;
    const int m_base = warp_m * 64, n_base = warp_n * 32;

    float acc[4][4][4];
#pragma unroll
    for (int i = 0; i < 4; i++)
#pragma unroll
        for (int j = 0; j < 4; j++)
#pragma unroll
            for (int q = 0; q < 4; q++) acc[i][j][q] = 0.0f;

    const u32 aoff = (u32)(m_base + (lane & 15)) * ROWB + (u32)(lane >> 4) * 16;
    const u32 boff = (u32)(n_base + (lane & 7) + ((lane >> 4) << 3)) * ROWB +
                     (u32)((lane >> 3) & 1) * 16;

    load_stage(sb + 0 * STAGEB, (const char*)g_Ah, (const char*)g_Al, 4096, m0,
               (const char*)g_Bh, (const char*)g_Bl, 4096, n0, 0, tid); CP_COMMIT();
    load_stage(sb + 1 * STAGEB, (const char*)g_Ah, (const char*)g_Al, 4096, m0,
               (const char*)g_Bh, (const char*)g_Bl, 4096, n0, 1, tid); CP_COMMIT();

#pragma unroll 1
    for (int c = 0; c < NCH_M; c++) {
        CP_WAIT1();
        __syncthreads();
        compute_chunk(sb + (u32)(c & 1) * STAGEB, aoff, boff, acc);
        __syncthreads();
        if (c + 2 < NCH_M) {
            load_stage(sb + (u32)(c & 1) * STAGEB,
                       (const char*)g_Ah, (const char*)g_Al, 4096, m0,
                       (const char*)g_Bh, (const char*)g_Bl, 4096, n0, c + 2, tid);
            CP_COMMIT();
        }
    }

    const int b = n0 >> 8;
#pragma unroll
    for (int mt = 0; mt < 4; mt++) {
        const int t0 = m0 + m_base + mt * 16 + (lane >> 2);
#pragma unroll
        for (int nt = 0; nt < 4; nt++) {
            const int gcol = (n0 & 255) + n_base + nt * 8 + 2 * (lane & 3);
            const int h = gcol >> 1;
            float* o0 = out + ((size_t)(b * TT + t0)) * HIDN + h;
            o0[0] = __fdividef(acc[mt][nt][0], acc[mt][nt][1]);
            o0[8 * HIDN] = __fdividef(acc[mt][nt][2], acc[mt][nt][3]);
        }
    }
}

// ---------------- launch ----------------
extern "C" void kernel_launch(void* const* d_in, const int* in_sizes, int n_in,
                              void* d_out, int out_size) {
    const float* x  = (const float*)d_in[0];
    const float* wk = (const float*)d_in[1];
    const float* bk = (const float*)d_in[2];
    const float* wv = (const float*)d_in[3];
    const float* bv = (const float*)d_in[4];
    const float* w  = (const float*)d_in[5];
    float* out = (float*)d_out;

    cudaFuncSetAttribute(k_mainTC, cudaFuncAttributeMaxDynamicSharedMemorySize, SMEMTOT);
    cudaFuncSetAttribute(k_projTC, cudaFuncAttributeMaxDynamicSharedMemorySize, SMEMTOT);

    k_expw2<<<4096, 256>>>(w);
    k_xsplit<<<16384, 256>>>(x);
    k_wsplit<<<dim3(32, 4), dim3(32, 8)>>>(wk, wv);
    k_projTC<<<dim3(128, 2), 256, SMEMTOT>>>(bk, bv);
    k_zT<<<dim3(64, 64), dim3(32, 8)>>>();
    k_mainTC<<<dim3(16, 16), 256, SMEMTOT>>>(out);
}

// round 6
// speedup vs baseline: 1.8195x; 1.3027x over previous
#include <cuda_runtime.h>
#include <cuda_fp16.h>
#include <cstdint>

#define TT   2048
#define DIMK 1024
#define HIDN 128

typedef unsigned long long u64;
typedef unsigned int u32;

// ---------------- scratch (__device__ globals; no runtime alloc) ------------
__device__ float  g_z[TT * TT];          // fp32 z[s][b*256+2h]=eK*V, odd=eK
__device__ __half g_ewh[TT * TT];        // exp(w) hi fp16 [t][s]
__device__ __half g_ewl[TT * TT];        // exp(w) lo fp16
__device__ __half g_zs[TT * TT];         // zT fp16 single [col][s]
__device__ __half g_xs[16384 * DIMK];    // x fp16 single [m][k]
__device__ __half g_wh[256 * DIMK];      // W^T interleaved hi [n][k]
__device__ __half g_wl[256 * DIMK];      // W^T interleaved lo

// ---------------- helpers ----------------------------------------------------
__device__ __forceinline__ u32 smem_u32(const void* p) {
    u32 a;
    asm("{ .reg .u64 t; cvta.to.shared.u64 t, %1; cvt.u32.u64 %0, t; }"
        : "=r"(a) : "l"(p));
    return a;
}
__device__ __forceinline__ void cp16(u32 s, const void* g) {
    asm volatile("cp.async.cg.shared.global [%0], [%1], 16;" :: "r"(s), "l"(g));
}
#define CP_COMMIT() asm volatile("cp.async.commit_group;" ::: "memory")
#define CP_WAIT2()  asm volatile("cp.async.wait_group 2;" ::: "memory")

__device__ __forceinline__ void ldsm4(u32 addr, u32& r0, u32& r1, u32& r2, u32& r3) {
    asm volatile("ldmatrix.sync.aligned.m8n8.x4.shared.b16 {%0,%1,%2,%3}, [%4];"
                 : "=r"(r0), "=r"(r1), "=r"(r2), "=r"(r3) : "r"(addr));
}
__device__ __forceinline__ void mma16816(float* d, u32 a0, u32 a1, u32 a2, u32 a3,
                                         u32 b0, u32 b1) {
    asm volatile(
        "mma.sync.aligned.m16n8k16.row.col.f32.f16.f16.f32 "
        "{%0,%1,%2,%3}, {%4,%5,%6,%7}, {%8,%9}, {%0,%1,%2,%3};"
        : "+f"(d[0]), "+f"(d[1]), "+f"(d[2]), "+f"(d[3])
        : "r"(a0), "r"(a1), "r"(a2), "r"(a3), "r"(b0), "r"(b1));
}
__device__ __forceinline__ void split_f16(float v, unsigned short& h, unsigned short& l) {
    __half hb = __float2half_rn(v);
    __half lb = __float2half_rn(v - __half2float(hb));
    h = __half_as_ushort(hb);
    l = __half_as_ushort(lb);
}

// ---------------- smem layout (3 operand mats per stage) --------------------
#define ROWB   80
#define MAT_B  (128 * ROWB)          // 10240
#define OFF_M0 0
#define OFF_M1 MAT_B
#define OFF_M2 (2 * MAT_B)
#define STAGEB (3 * MAT_B)           // 30720
#define NSTG   3
#define SMEMTOT (NSTG * STAGEB)      // 92160 -> 2 CTAs/SM

// 256-thread loader: 1536 cp16 per stage -> 6 per thread.
__device__ __forceinline__ void load_stage3(
    u32 dst,
    const char* p0, size_t s0, int b0,
    const char* p1, size_t s1, int b1,
    const char* p2, size_t s2, int b2,
    int chunk, int tid) {
    const size_t cb = (size_t)chunk * 64;
#pragma unroll
    for (int i = 0; i < 6; i++) {
        int idx = tid * 6 + i;            // 0..1535
        int mat = idx / 512;
        int rr = (idx & 511) >> 2;
        int ko = idx & 3;
        const char* p = (mat == 0) ? p0 : (mat == 1) ? p1 : p2;
        size_t st = (mat == 0) ? s0 : (mat == 1) ? s1 : s2;
        int bb = (mat == 0) ? b0 : (mat == 1) ? b1 : b2;
        cp16(dst + (u32)mat * MAT_B + (u32)rr * ROWB + (u32)ko * 16,
             p + (size_t)(bb + rr) * st + cb + (size_t)ko * 16);
    }
}

// main: A split (mats 0,1), B single (mat 2).  warp tile 64x32.
__device__ __forceinline__ void compute_main(u32 s0, u32 aoff, u32 boff,
                                             float (&acc)[4][4][4]) {
#pragma unroll
    for (int ks = 0; ks < 2; ks++) {
        const u32 ak = aoff + (u32)ks * 32;
        const u32 bko = boff + (u32)ks * 32;
        u32 Af[4][4], Bf[2][4];
#pragma unroll
        for (int mt = 0; mt < 4; mt++)
            ldsm4(s0 + OFF_M0 + ak + (u32)mt * (16 * ROWB),
                  Af[mt][0], Af[mt][1], Af[mt][2], Af[mt][3]);
#pragma unroll
        for (int np = 0; np < 2; np++)
            ldsm4(s0 + OFF_M2 + bko + (u32)np * (16 * ROWB),
                  Bf[np][0], Bf[np][1], Bf[np][2], Bf[np][3]);
#pragma unroll
        for (int mt = 0; mt < 4; mt++)
#pragma unroll
            for (int nt = 0; nt < 4; nt++)
                mma16816(acc[mt][nt], Af[mt][0], Af[mt][1], Af[mt][2], Af[mt][3],
                         Bf[nt >> 1][(nt & 1) * 2], Bf[nt >> 1][(nt & 1) * 2 + 1]);
#pragma unroll
        for (int mt = 0; mt < 4; mt++)
            ldsm4(s0 + OFF_M1 + ak + (u32)mt * (16 * ROWB),
                  Af[mt][0], Af[mt][1], Af[mt][2], Af[mt][3]);
#pragma unroll
        for (int mt = 0; mt < 4; mt++)
#pragma unroll
            for (int nt = 0; nt < 4; nt++)
                mma16816(acc[mt][nt], Af[mt][0], Af[mt][1], Af[mt][2], Af[mt][3],
                         Bf[nt >> 1][(nt & 1) * 2], Bf[nt >> 1][(nt & 1) * 2 + 1]);
    }
}

// proj: A single (mat 0), B split (mats 1,2).
__device__ __forceinline__ void compute_proj(u32 s0, u32 aoff, u32 boff,
                                             float (&acc)[4][4][4]) {
#pragma unroll
    for (int ks = 0; ks < 2; ks++) {
        const u32 ak = aoff + (u32)ks * 32;
        const u32 bko = boff + (u32)ks * 32;
        u32 Af[4][4], Bh[2][4], Bl[2][4];
#pragma unroll
        for (int mt = 0; mt < 4; mt++)
            ldsm4(s0 + OFF_M0 + ak + (u32)mt * (16 * ROWB),
                  Af[mt][0], Af[mt][1], Af[mt][2], Af[mt][3]);
#pragma unroll
        for (int np = 0; np < 2; np++)
            ldsm4(s0 + OFF_M1 + bko + (u32)np * (16 * ROWB),
                  Bh[np][0], Bh[np][1], Bh[np][2], Bh[np][3]);
#pragma unroll
        for (int np = 0; np < 2; np++)
            ldsm4(s0 + OFF_M2 + bko + (u32)np * (16 * ROWB),
                  Bl[np][0], Bl[np][1], Bl[np][2], Bl[np][3]);
#pragma unroll
        for (int mt = 0; mt < 4; mt++)
#pragma unroll
            for (int nt = 0; nt < 4; nt++)
                mma16816(acc[mt][nt], Af[mt][0], Af[mt][1], Af[mt][2], Af[mt][3],
                         Bh[nt >> 1][(nt & 1) * 2], Bh[nt >> 1][(nt & 1) * 2 + 1]);
#pragma unroll
        for (int mt = 0; mt < 4; mt++)
#pragma unroll
            for (int nt = 0; nt < 4; nt++)
                mma16816(acc[mt][nt], Af[mt][0], Af[mt][1], Af[mt][2], Af[mt][3],
                         Bl[nt >> 1][(nt & 1) * 2], Bl[nt >> 1][(nt & 1) * 2 + 1]);
    }
}

// ---------------- elementwise prep kernels -----------------------------------
__global__ void k_expw2(const float* __restrict__ w) {
    int i = blockIdx.x * blockDim.x + threadIdx.x;   // 1M float4s
    float4 v = ((const float4*)w)[i];
    float e[4] = {__expf(v.x), __expf(v.y), __expf(v.z), __expf(v.w)};
    ushort4 H, L;
    unsigned short* hp = &H.x;
    unsigned short* lp = &L.x;
#pragma unroll
    for (int q = 0; q < 4; q++) split_f16(e[q], hp[q], lp[q]);
    ((ushort4*)g_ewh)[i] = H;
    ((ushort4*)g_ewl)[i] = L;
}

__global__ void k_xs(const float* __restrict__ x) {
    int i = blockIdx.x * blockDim.x + threadIdx.x;   // 4M float4s
    float4 v = ((const float4*)x)[i];
    ushort4 H;
    H.x = __half_as_ushort(__float2half_rn(v.x));
    H.y = __half_as_ushort(__float2half_rn(v.y));
    H.z = __half_as_ushort(__float2half_rn(v.z));
    H.w = __half_as_ushort(__float2half_rn(v.w));
    ((ushort4*)g_xs)[i] = H;
}

__global__ void k_wsplit(const float* __restrict__ wk, const float* __restrict__ wv) {
    __shared__ float tK[32][33], tV[32][33];
    const int bs = blockIdx.x << 5;   // k block
    const int bh = blockIdx.y << 5;   // h block
    const int tx = threadIdx.x, ty = threadIdx.y;
#pragma unroll
    for (int i = 0; i < 32; i += 8) {
        tK[ty + i][tx] = wk[(bs + ty + i) * HIDN + bh + tx];
        tV[ty + i][tx] = wv[(bs + ty + i) * HIDN + bh + tx];
    }
    __syncthreads();
#pragma unroll
    for (int i = 0; i < 32; i += 8) {
        int hl = ty + i;
        unsigned short h, l;
        split_f16(tK[tx][hl], h, l);
        size_t oK = (size_t)(2 * (bh + hl)) * DIMK + bs + tx;
        g_wh[oK] = __ushort_as_half(h);
        g_wl[oK] = __ushort_as_half(l);
        split_f16(tV[tx][hl], h, l);
        g_wh[oK + DIMK] = __ushort_as_half(h);
        g_wl[oK + DIMK] = __ushort_as_half(l);
    }
}

__global__ void k_zTs() {
    __shared__ float tile[32][33];
    const int bc = blockIdx.x << 5;   // col block
    const int bs = blockIdx.y << 5;   // s block
    const int tx = threadIdx.x, ty = threadIdx.y;
#pragma unroll
    for (int i = 0; i < 32; i += 8)
        tile[ty + i][tx] = g_z[(size_t)(bs + ty + i) * TT + bc + tx];
    __syncthreads();
#pragma unroll
    for (int i = 0; i < 32; i += 8) {
        size_t o = (size_t)(bc + ty + i) * TT + bs + tx;
        g_zs[o] = __float2half_rn(tile[tx][ty + i]);
    }
}

// ---------------- GEMM kernels (256 thr, 8 warps, 2 CTAs/SM, 3-stage) -------
#define NCH_P (DIMK / 32)   // 32
__global__ __launch_bounds__(256, 2) void k_projTC(
    const float* __restrict__ bk, const float* __restrict__ bv) {
    extern __shared__ char smem[];
    const u32 sb = smem_u32(smem);
    const int tid = threadIdx.x;
    const int wid = tid >> 5, lane = tid & 31;
    const int m0 = blockIdx.x << 7;
    const int n0 = blockIdx.y << 7;
    const int warp_m = wid >> 2, warp_n = wid & 3;
    const int m_base = warp_m * 64, n_base = warp_n * 32;

    float acc[4][4][4];
#pragma unroll
    for (int i = 0; i < 4; i++)
#pragma unroll
        for (int j = 0; j < 4; j++)
#pragma unroll
            for (int q = 0; q < 4; q++) acc[i][j][q] = 0.0f;

    const u32 aoff = (u32)(m_base + (lane & 15)) * ROWB + (u32)(lane >> 4) * 16;
    const u32 boff = (u32)(n_base + (lane & 7) + ((lane >> 4) << 3)) * ROWB +
                     (u32)((lane >> 3) & 1) * 16;

#pragma unroll
    for (int p = 0; p < NSTG; p++) {
        load_stage3(sb + (u32)p * STAGEB,
                    (const char*)g_xs, 2048, m0,
                    (const char*)g_wh, 2048, n0,
                    (const char*)g_wl, 2048, n0, p, tid);
        CP_COMMIT();
    }

#pragma unroll 1
    for (int c = 0; c < NCH_P; c++) {
        CP_WAIT2();
        __syncthreads();
        compute_proj(sb + (u32)(c % NSTG) * STAGEB, aoff, boff, acc);
        __syncthreads();
        if (c + NSTG < NCH_P) {
            load_stage3(sb + (u32)(c % NSTG) * STAGEB,
                        (const char*)g_xs, 2048, m0,
                        (const char*)g_wh, 2048, n0,
                        (const char*)g_wl, 2048, n0, c + NSTG, tid);
            CP_COMMIT();
        }
    }

    const int b = m0 >> 11;
#pragma unroll
    for (int mt = 0; mt < 4; mt++) {
        const int m = m0 + m_base + mt * 16 + (lane >> 2);
        const int s = m & 2047;
#pragma unroll
        for (int nt = 0; nt < 4; nt++) {
            const int c0 = n0 + n_base + nt * 8 + 2 * (lane & 3);
            const int h = c0 >> 1;
            const float bkh = bk[h], bvh = bv[h];
            float ek0 = __expf(acc[mt][nt][0] + bkh);
            float v0 = acc[mt][nt][1] + bvh;
            float ek1 = __expf(acc[mt][nt][2] + bkh);
            float v1 = acc[mt][nt][3] + bvh;
            float* d0 = g_z + (size_t)s * TT + b * 256 + c0;
            *(float2*)d0 = make_float2(ek0 * v0, ek0);
            *(float2*)(d0 + 8 * TT) = make_float2(ek1 * v1, ek1);
        }
    }
}

#define NCH_M (TT / 32)   // 64
__global__ __launch_bounds__(256, 2) void k_mainTC(float* __restrict__ out) {
    extern __shared__ char smem[];
    const u32 sb = smem_u32(smem);
    const int tid = threadIdx.x;
    const int wid = tid >> 5, lane = tid & 31;
    const int m0 = blockIdx.x << 7;
    const int n0 = blockIdx.y << 7;
    const int warp_m = wid >> 2, warp_n = wid & 3;
    const int m_base = warp_m * 64, n_base = warp_n * 32;

    float acc[4][4][4];
#pragma unroll
    for (int i = 0; i < 4; i++)
#pragma unroll
        for (int j = 0; j < 4; j++)
#pragma unroll
            for (int q = 0; q < 4; q++) acc[i][j][q] = 0.0f;

    const u32 aoff = (u32)(m_base + (lane & 15)) * ROWB + (u32)(lane >> 4) * 16;
    const u32 boff = (u32)(n_base + (lane & 7) + ((lane >> 4) << 3)) * ROWB +
                     (u32)((lane >> 3) & 1) * 16;

#pragma unroll
    for (int p = 0; p < NSTG; p++) {
        load_stage3(sb + (u32)p * STAGEB,
                    (const char*)g_ewh, 4096, m0,
                    (const char*)g_ewl, 4096, m0,
                    (const char*)g_zs, 4096, n0, p, tid);
        CP_COMMIT();
    }

#pragma unroll 1
    for (int c = 0; c < NCH_M; c++) {
        CP_WAIT2();
        __syncthreads();
        compute_main(sb + (u32)(c % NSTG) * STAGEB, aoff, boff, acc);
        __syncthreads();
        if (c + NSTG < NCH_M) {
            load_stage3(sb + (u32)(c % NSTG) * STAGEB,
                        (const char*)g_ewh, 4096, m0,
                        (const char*)g_ewl, 4096, m0,
                        (const char*)g_zs, 4096, n0, c + NSTG, tid);
            CP_COMMIT();
        }
    }

    const int b = n0 >> 8;
#pragma unroll
    for (int mt = 0; mt < 4; mt++) {
        const int t0 = m0 + m_base + mt * 16 + (lane >> 2);
#pragma unroll
        for (int nt = 0; nt < 4; nt++) {
            const int gcol = (n0 & 255) + n_base + nt * 8 + 2 * (lane & 3);
            const int h = gcol >> 1;
            float* o0 = out + ((size_t)(b * TT + t0)) * HIDN + h;
            o0[0] = __fdividef(acc[mt][nt][0], acc[mt][nt][1]);
            o0[8 * HIDN] = __fdividef(acc[mt][nt][2], acc[mt][nt][3]);
        }
    }
}

// ---------------- launch ----------------
extern "C" void kernel_launch(void* const* d_in, const int* in_sizes, int n_in,
                              void* d_out, int out_size) {
    const float* x  = (const float*)d_in[0];
    const float* wk = (const float*)d_in[1];
    const float* bk = (const float*)d_in[2];
    const float* wv = (const float*)d_in[3];
    const float* bv = (const float*)d_in[4];
    const float* w  = (const float*)d_in[5];
    float* out = (float*)d_out;

    cudaFuncSetAttribute(k_mainTC, cudaFuncAttributeMaxDynamicSharedMemorySize, SMEMTOT);
    cudaFuncSetAttribute(k_projTC, cudaFuncAttributeMaxDynamicSharedMemorySize, SMEMTOT);

    k_expw2<<<4096, 256>>>(w);
    k_xs<<<16384, 256>>>(x);
    k_wsplit<<<dim3(32, 4), dim3(32, 8)>>>(wk, wv);
    k_projTC<<<dim3(128, 2), 256, SMEMTOT>>>(bk, bv);
    k_zTs<<<dim3(64, 64), dim3(32, 8)>>>();
    k_mainTC<<<dim3(16, 16), 256, SMEMTOT>>>(out);
}

// round 7
// speedup vs baseline: 1.8473x; 1.0153x over previous
#include <cuda_runtime.h>
#include <cuda_fp16.h>
#include <cstdint>

#define TT   2048
#define DIMK 1024
#define HIDN 128

typedef unsigned long long u64;
typedef unsigned int u32;

// ---------------- scratch (__device__ globals; no runtime alloc) ------------
__device__ float  g_z[TT * TT];          // fp32 z[s][b*256+2h]=eK*V, odd=eK
__device__ __half g_ewh[TT * TT];        // exp(w) hi fp16 [t][s]
__device__ __half g_ewl[TT * TT];        // exp(w) lo fp16
__device__ __half g_zs[TT * TT];         // zT fp16 single [col][s]
__device__ __half g_xs[16384 * DIMK];    // x fp16 single [m][k]
__device__ __half g_wh[256 * DIMK];      // W^T interleaved hi [n][k]
__device__ __half g_wl[256 * DIMK];      // W^T interleaved lo

// ---------------- helpers ----------------------------------------------------
__device__ __forceinline__ u32 smem_u32(const void* p) {
    u32 a;
    asm("{ .reg .u64 t; cvta.to.shared.u64 t, %1; cvt.u32.u64 %0, t; }"
        : "=r"(a) : "l"(p));
    return a;
}
__device__ __forceinline__ void cp16(u32 s, const void* g) {
    asm volatile("cp.async.cg.shared.global [%0], [%1], 16;" :: "r"(s), "l"(g));
}
#define CP_COMMIT() asm volatile("cp.async.commit_group;" ::: "memory")
#define CP_WAIT1()  asm volatile("cp.async.wait_group 1;" ::: "memory")

__device__ __forceinline__ void ldsm4(u32 addr, u32& r0, u32& r1, u32& r2, u32& r3) {
    asm volatile("ldmatrix.sync.aligned.m8n8.x4.shared.b16 {%0,%1,%2,%3}, [%4];"
                 : "=r"(r0), "=r"(r1), "=r"(r2), "=r"(r3) : "r"(addr));
}
__device__ __forceinline__ void mma16816(float* d, u32 a0, u32 a1, u32 a2, u32 a3,
                                         u32 b0, u32 b1) {
    asm volatile(
        "mma.sync.aligned.m16n8k16.row.col.f32.f16.f16.f32 "
        "{%0,%1,%2,%3}, {%4,%5,%6,%7}, {%8,%9}, {%0,%1,%2,%3};"
        : "+f"(d[0]), "+f"(d[1]), "+f"(d[2]), "+f"(d[3])
        : "r"(a0), "r"(a1), "r"(a2), "r"(a3), "r"(b0), "r"(b1));
}
__device__ __forceinline__ void split_f16(float v, unsigned short& h, unsigned short& l) {
    __half hb = __float2half_rn(v);
    __half lb = __float2half_rn(v - __half2float(hb));
    h = __half_as_ushort(hb);
    l = __half_as_ushort(lb);
}

// ---------------- smem layout (3 operand mats per stage) --------------------
#define ROWB   80
#define MAT_B  (128 * ROWB)          // 10240
#define OFF_M0 0
#define OFF_M1 MAT_B
#define OFF_M2 (2 * MAT_B)
#define STAGEB (3 * MAT_B)           // 30720
#define NSTG   3
#define SMEMTOT (NSTG * STAGEB)      // 92160 -> 2 CTAs/SM

// 256-thread loader: 1536 cp16 per stage -> 6 per thread.
__device__ __forceinline__ void load_stage3(
    u32 dst,
    const char* p0, size_t s0, int b0,
    const char* p1, size_t s1, int b1,
    const char* p2, size_t s2, int b2,
    int chunk, int tid) {
    const size_t cb = (size_t)chunk * 64;
#pragma unroll
    for (int i = 0; i < 6; i++) {
        int idx = tid * 6 + i;            // 0..1535
        int mat = idx / 512;
        int rr = (idx & 511) >> 2;
        int ko = idx & 3;
        const char* p = (mat == 0) ? p0 : (mat == 1) ? p1 : p2;
        size_t st = (mat == 0) ? s0 : (mat == 1) ? s1 : s2;
        int bb = (mat == 0) ? b0 : (mat == 1) ? b1 : b2;
        cp16(dst + (u32)mat * MAT_B + (u32)rr * ROWB + (u32)ko * 16,
             p + (size_t)(bb + rr) * st + cb + (size_t)ko * 16);
    }
}

// main: A split (mats 0,1), B single (mat 2).  warp tile 64x32.
__device__ __forceinline__ void compute_main(u32 s0, u32 aoff, u32 boff,
                                             float (&acc)[4][4][4]) {
#pragma unroll
    for (int ks = 0; ks < 2; ks++) {
        const u32 ak = aoff + (u32)ks * 32;
        const u32 bko = boff + (u32)ks * 32;
        u32 Af[4][4], Bf[2][4];
#pragma unroll
        for (int mt = 0; mt < 4; mt++)
            ldsm4(s0 + OFF_M0 + ak + (u32)mt * (16 * ROWB),
                  Af[mt][0], Af[mt][1], Af[mt][2], Af[mt][3]);
#pragma unroll
        for (int np = 0; np < 2; np++)
            ldsm4(s0 + OFF_M2 + bko + (u32)np * (16 * ROWB),
                  Bf[np][0], Bf[np][1], Bf[np][2], Bf[np][3]);
#pragma unroll
        for (int mt = 0; mt < 4; mt++)
#pragma unroll
            for (int nt = 0; nt < 4; nt++)
                mma16816(acc[mt][nt], Af[mt][0], Af[mt][1], Af[mt][2], Af[mt][3],
                         Bf[nt >> 1][(nt & 1) * 2], Bf[nt >> 1][(nt & 1) * 2 + 1]);
#pragma unroll
        for (int mt = 0; mt < 4; mt++)
            ldsm4(s0 + OFF_M1 + ak + (u32)mt * (16 * ROWB),
                  Af[mt][0], Af[mt][1], Af[mt][2], Af[mt][3]);
#pragma unroll
        for (int mt = 0; mt < 4; mt++)
#pragma unroll
            for (int nt = 0; nt < 4; nt++)
                mma16816(acc[mt][nt], Af[mt][0], Af[mt][1], Af[mt][2], Af[mt][3],
                         Bf[nt >> 1][(nt & 1) * 2], Bf[nt >> 1][(nt & 1) * 2 + 1]);
    }
}

// proj: A single (mat 0), B split (mats 1,2).
__device__ __forceinline__ void compute_proj(u32 s0, u32 aoff, u32 boff,
                                             float (&acc)[4][4][4]) {
#pragma unroll
    for (int ks = 0; ks < 2; ks++) {
        const u32 ak = aoff + (u32)ks * 32;
        const u32 bko = boff + (u32)ks * 32;
        u32 Af[4][4], Bh[2][4], Bl[2][4];
#pragma unroll
        for (int mt = 0; mt < 4; mt++)
            ldsm4(s0 + OFF_M0 + ak + (u32)mt * (16 * ROWB),
                  Af[mt][0], Af[mt][1], Af[mt][2], Af[mt][3]);
#pragma unroll
        for (int np = 0; np < 2; np++)
            ldsm4(s0 + OFF_M1 + bko + (u32)np * (16 * ROWB),
                  Bh[np][0], Bh[np][1], Bh[np][2], Bh[np][3]);
#pragma unroll
        for (int np = 0; np < 2; np++)
            ldsm4(s0 + OFF_M2 + bko + (u32)np * (16 * ROWB),
                  Bl[np][0], Bl[np][1], Bl[np][2], Bl[np][3]);
#pragma unroll
        for (int mt = 0; mt < 4; mt++)
#pragma unroll
            for (int nt = 0; nt < 4; nt++)
                mma16816(acc[mt][nt], Af[mt][0], Af[mt][1], Af[mt][2], Af[mt][3],
                         Bh[nt >> 1][(nt & 1) * 2], Bh[nt >> 1][(nt & 1) * 2 + 1]);
#pragma unroll
        for (int mt = 0; mt < 4; mt++)
#pragma unroll
            for (int nt = 0; nt < 4; nt++)
                mma16816(acc[mt][nt], Af[mt][0], Af[mt][1], Af[mt][2], Af[mt][3],
                         Bl[nt >> 1][(nt & 1) * 2], Bl[nt >> 1][(nt & 1) * 2 + 1]);
    }
}

// ---------------- elementwise prep kernels -----------------------------------
__global__ void k_expw2(const float* __restrict__ w) {
    int i = blockIdx.x * blockDim.x + threadIdx.x;   // 1M float4s
    float4 v = ((const float4*)w)[i];
    float e[4] = {__expf(v.x), __expf(v.y), __expf(v.z), __expf(v.w)};
    ushort4 H, L;
    unsigned short* hp = &H.x;
    unsigned short* lp = &L.x;
#pragma unroll
    for (int q = 0; q < 4; q++) split_f16(e[q], hp[q], lp[q]);
    ((ushort4*)g_ewh)[i] = H;
    ((ushort4*)g_ewl)[i] = L;
}

__global__ void k_xs(const float* __restrict__ x) {
    int i = blockIdx.x * blockDim.x + threadIdx.x;   // 4M float4s
    float4 v = ((const float4*)x)[i];
    ushort4 H;
    H.x = __half_as_ushort(__float2half_rn(v.x));
    H.y = __half_as_ushort(__float2half_rn(v.y));
    H.z = __half_as_ushort(__float2half_rn(v.z));
    H.w = __half_as_ushort(__float2half_rn(v.w));
    ((ushort4*)g_xs)[i] = H;
}

__global__ void k_wsplit(const float* __restrict__ wk, const float* __restrict__ wv) {
    __shared__ float tK[32][33], tV[32][33];
    const int bs = blockIdx.x << 5;   // k block
    const int bh = blockIdx.y << 5;   // h block
    const int tx = threadIdx.x, ty = threadIdx.y;
#pragma unroll
    for (int i = 0; i < 32; i += 8) {
        tK[ty + i][tx] = wk[(bs + ty + i) * HIDN + bh + tx];
        tV[ty + i][tx] = wv[(bs + ty + i) * HIDN + bh + tx];
    }
    __syncthreads();
#pragma unroll
    for (int i = 0; i < 32; i += 8) {
        int hl = ty + i;
        unsigned short h, l;
        split_f16(tK[tx][hl], h, l);
        size_t oK = (size_t)(2 * (bh + hl)) * DIMK + bs + tx;
        g_wh[oK] = __ushort_as_half(h);
        g_wl[oK] = __ushort_as_half(l);
        split_f16(tV[tx][hl], h, l);
        g_wh[oK + DIMK] = __ushort_as_half(h);
        g_wl[oK + DIMK] = __ushort_as_half(l);
    }
}

__global__ void k_zTs() {
    __shared__ float tile[32][33];
    const int bc = blockIdx.x << 5;   // col block
    const int bs = blockIdx.y << 5;   // s block
    const int tx = threadIdx.x, ty = threadIdx.y;
#pragma unroll
    for (int i = 0; i < 32; i += 8)
        tile[ty + i][tx] = g_z[(size_t)(bs + ty + i) * TT + bc + tx];
    __syncthreads();
#pragma unroll
    for (int i = 0; i < 32; i += 8) {
        size_t o = (size_t)(bc + ty + i) * TT + bs + tx;
        g_zs[o] = __float2half_rn(tile[tx][ty + i]);
    }
}

// ---------------- GEMM kernels: 1 barrier/chunk, loads before compute -------
#define NCH_P (DIMK / 32)   // 32
__global__ __launch_bounds__(256, 2) void k_projTC(
    const float* __restrict__ bk, const float* __restrict__ bv) {
    extern __shared__ char smem[];
    const u32 sb = smem_u32(smem);
    const int tid = threadIdx.x;
    const int wid = tid >> 5, lane = tid & 31;
    const int m0 = blockIdx.x << 7;
    const int n0 = blockIdx.y << 7;
    const int warp_m = wid >> 2, warp_n = wid & 3;
    const int m_base = warp_m * 64, n_base = warp_n * 32;

    float acc[4][4][4];
#pragma unroll
    for (int i = 0; i < 4; i++)
#pragma unroll
        for (int j = 0; j < 4; j++)
#pragma unroll
            for (int q = 0; q < 4; q++) acc[i][j][q] = 0.0f;

    const u32 aoff = (u32)(m_base + (lane & 15)) * ROWB + (u32)(lane >> 4) * 16;
    const u32 boff = (u32)(n_base + (lane & 7) + ((lane >> 4) << 3)) * ROWB +
                     (u32)((lane >> 3) & 1) * 16;

    // prologue: 2 chunks in flight
    load_stage3(sb + 0 * STAGEB, (const char*)g_xs, 2048, m0,
                (const char*)g_wh, 2048, n0, (const char*)g_wl, 2048, n0, 0, tid);
    CP_COMMIT();
    load_stage3(sb + 1 * STAGEB, (const char*)g_xs, 2048, m0,
                (const char*)g_wh, 2048, n0, (const char*)g_wl, 2048, n0, 1, tid);
    CP_COMMIT();

#pragma unroll 1
    for (int c = 0; c < NCH_P; c++) {
        CP_WAIT1();            // chunk c arrived (chunk c+1 may still fly)
        __syncthreads();       // + all warps done reading buffer (c-1)%3
        if (c + 2 < NCH_P) {
            load_stage3(sb + (u32)((c + 2) % NSTG) * STAGEB,
                        (const char*)g_xs, 2048, m0,
                        (const char*)g_wh, 2048, n0,
                        (const char*)g_wl, 2048, n0, c + 2, tid);
            CP_COMMIT();
        }
        compute_proj(sb + (u32)(c % NSTG) * STAGEB, aoff, boff, acc);
    }

    const int b = m0 >> 11;
#pragma unroll
    for (int mt = 0; mt < 4; mt++) {
        const int m = m0 + m_base + mt * 16 + (lane >> 2);
        const int s = m & 2047;
#pragma unroll
        for (int nt = 0; nt < 4; nt++) {
            const int c0 = n0 + n_base + nt * 8 + 2 * (lane & 3);
            const int h = c0 >> 1;
            const float bkh = bk[h], bvh = bv[h];
            float ek0 = __expf(acc[mt][nt][0] + bkh);
            float v0 = acc[mt][nt][1] + bvh;
            float ek1 = __expf(acc[mt][nt][2] + bkh);
            float v1 = acc[mt][nt][3] + bvh;
            float* d0 = g_z + (size_t)s * TT + b * 256 + c0;
            *(float2*)d0 = make_float2(ek0 * v0, ek0);
            *(float2*)(d0 + 8 * TT) = make_float2(ek1 * v1, ek1);
        }
    }
}

#define NCH_M (TT / 32)   // 64
__global__ __launch_bounds__(256, 2) void k_mainTC(float* __restrict__ out) {
    extern __shared__ char smem[];
    const u32 sb = smem_u32(smem);
    const int tid = threadIdx.x;
    const int wid = tid >> 5, lane = tid & 31;
    const int m0 = blockIdx.x << 7;
    const int n0 = blockIdx.y << 7;
    const int warp_m = wid >> 2, warp_n = wid & 3;
    const int m_base = warp_m * 64, n_base = warp_n * 32;

    float acc[4][4][4];
#pragma unroll
    for (int i = 0; i < 4; i++)
#pragma unroll
        for (int j = 0; j < 4; j++)
#pragma unroll
            for (int q = 0; q < 4; q++) acc[i][j][q] = 0.0f;

    const u32 aoff = (u32)(m_base + (lane & 15)) * ROWB + (u32)(lane >> 4) * 16;
    const u32 boff = (u32)(n_base + (lane & 7) + ((lane >> 4) << 3)) * ROWB +
                     (u32)((lane >> 3) & 1) * 16;

    load_stage3(sb + 0 * STAGEB, (const char*)g_ewh, 4096, m0,
                (const char*)g_ewl, 4096, m0, (const char*)g_zs, 4096, n0, 0, tid);
    CP_COMMIT();
    load_stage3(sb + 1 * STAGEB, (const char*)g_ewh, 4096, m0,
                (const char*)g_ewl, 4096, m0, (const char*)g_zs, 4096, n0, 1, tid);
    CP_COMMIT();

#pragma unroll 1
    for (int c = 0; c < NCH_M; c++) {
        CP_WAIT1();
        __syncthreads();
        if (c + 2 < NCH_M) {
            load_stage3(sb + (u32)((c + 2) % NSTG) * STAGEB,
                        (const char*)g_ewh, 4096, m0,
                        (const char*)g_ewl, 4096, m0,
                        (const char*)g_zs, 4096, n0, c + 2, tid);
            CP_COMMIT();
        }
        compute_main(sb + (u32)(c % NSTG) * STAGEB, aoff, boff, acc);
    }

    const int b = n0 >> 8;
#pragma unroll
    for (int mt = 0; mt < 4; mt++) {
        const int t0 = m0 + m_base + mt * 16 + (lane >> 2);
#pragma unroll
        for (int nt = 0; nt < 4; nt++) {
            const int gcol = (n0 & 255) + n_base + nt * 8 + 2 * (lane & 3);
            const int h = gcol >> 1;
            float* o0 = out + ((size_t)(b * TT + t0)) * HIDN + h;
            o0[0] = __fdividef(acc[mt][nt][0], acc[mt][nt][1]);
            o0[8 * HIDN] = __fdividef(acc[mt][nt][2], acc[mt][nt][3]);
        }
    }
}

// ---------------- launch ----------------
extern "C" void kernel_launch(void* const* d_in, const int* in_sizes, int n_in,
                              void* d_out, int out_size) {
    const float* x  = (const float*)d_in[0];
    const float* wk = (const float*)d_in[1];
    const float* bk = (const float*)d_in[2];
    const float* wv = (const float*)d_in[3];
    const float* bv = (const float*)d_in[4];
    const float* w  = (const float*)d_in[5];
    float* out = (float*)d_out;

    cudaFuncSetAttribute(k_mainTC, cudaFuncAttributeMaxDynamicSharedMemorySize, SMEMTOT);
    cudaFuncSetAttribute(k_projTC, cudaFuncAttributeMaxDynamicSharedMemorySize, SMEMTOT);

    k_expw2<<<4096, 256>>>(w);
    k_xs<<<16384, 256>>>(x);
    k_wsplit<<<dim3(32, 4), dim3(32, 8)>>>(wk, wv);
    k_projTC<<<dim3(128, 2), 256, SMEMTOT>>>(bk, bv);
    k_zTs<<<dim3(64, 64), dim3(32, 8)>>>();
    k_mainTC<<<dim3(16, 16), 256, SMEMTOT>>>(out);
}

// round 8
// speedup vs baseline: 2.9694x; 1.6075x over previous
#include <cuda_runtime.h>
#include <cuda_fp16.h>
#include <cstdint>

#define TT   2048
#define DIMK 1024
#define HIDN 128

typedef unsigned long long u64;
typedef unsigned int u32;

// ---------------- scratch (__device__ globals; no runtime alloc) ------------
__device__ __half g_ewh[TT * TT];        // exp(w) fp16 [t][s]
__device__ __half g_zs[TT * TT];         // zT fp16 [col][s], col=b*256+{2h:eKV,2h+1:eK}
__device__ __half g_xs[16384 * DIMK];    // x fp16 [m][k]
__device__ __half g_wh[256 * DIMK];      // W^T interleaved fp16 [n][k]

// ---------------- helpers ----------------------------------------------------
__device__ __forceinline__ u32 smem_u32(const void* p) {
    u32 a;
    asm("{ .reg .u64 t; cvta.to.shared.u64 t, %1; cvt.u32.u64 %0, t; }"
        : "=r"(a) : "l"(p));
    return a;
}
__device__ __forceinline__ void cp16(u32 s, const void* g) {
    asm volatile("cp.async.cg.shared.global [%0], [%1], 16;" :: "r"(s), "l"(g));
}
#define CP_COMMIT() asm volatile("cp.async.commit_group;" ::: "memory")
#define CP_WAIT2()  asm volatile("cp.async.wait_group 2;" ::: "memory")

__device__ __forceinline__ void ldsm4(u32 addr, u32& r0, u32& r1, u32& r2, u32& r3) {
    asm volatile("ldmatrix.sync.aligned.m8n8.x4.shared.b16 {%0,%1,%2,%3}, [%4];"
                 : "=r"(r0), "=r"(r1), "=r"(r2), "=r"(r3) : "r"(addr));
}
__device__ __forceinline__ void mma16816(float* d, u32 a0, u32 a1, u32 a2, u32 a3,
                                         u32 b0, u32 b1) {
    asm volatile(
        "mma.sync.aligned.m16n8k16.row.col.f32.f16.f16.f32 "
        "{%0,%1,%2,%3}, {%4,%5,%6,%7}, {%8,%9}, {%0,%1,%2,%3};"
        : "+f"(d[0]), "+f"(d[1]), "+f"(d[2]), "+f"(d[3])
        : "r"(a0), "r"(a1), "r"(a2), "r"(a3), "r"(b0), "r"(b1));
}

// ---------------- smem layout (2 operand mats per stage, 4 stages) ----------
#define ROWB   80
#define MAT_B  (128 * ROWB)          // 10240
#define OFF_M0 0
#define OFF_M1 MAT_B
#define STAGEB (2 * MAT_B)           // 20480
#define NSTG   4
#define SMEMTOT (NSTG * STAGEB)      // 81920 -> 2 CTAs/SM

// 256-thread loader: 1024 cp16 per stage -> 4 per thread.
__device__ __forceinline__ void load_stage2(
    u32 dst,
    const char* p0, size_t s0, int b0,
    const char* p1, size_t s1, int b1,
    int chunk, int tid) {
    const size_t cb = (size_t)chunk * 64;
#pragma unroll
    for (int i = 0; i < 4; i++) {
        int idx = tid * 4 + i;            // 0..1023
        int mat = idx >> 9;
        int rr = (idx & 511) >> 2;
        int ko = idx & 3;
        const char* p = mat ? p1 : p0;
        size_t st = mat ? s1 : s0;
        int bb = mat ? b1 : b0;
        cp16(dst + (u32)mat * MAT_B + (u32)rr * ROWB + (u32)ko * 16,
             p + (size_t)(bb + rr) * st + cb + (size_t)ko * 16);
    }
}

// single-pass fp16 compute for one k=32 chunk (warp tile 64x32)
__device__ __forceinline__ void compute_sp(u32 s0, u32 aoff, u32 boff,
                                           float (&acc)[4][4][4]) {
#pragma unroll
    for (int ks = 0; ks < 2; ks++) {
        const u32 ak = aoff + (u32)ks * 32;
        const u32 bko = boff + (u32)ks * 32;
        u32 Af[4][4], Bf[2][4];
#pragma unroll
        for (int mt = 0; mt < 4; mt++)
            ldsm4(s0 + OFF_M0 + ak + (u32)mt * (16 * ROWB),
                  Af[mt][0], Af[mt][1], Af[mt][2], Af[mt][3]);
#pragma unroll
        for (int np = 0; np < 2; np++)
            ldsm4(s0 + OFF_M1 + bko + (u32)np * (16 * ROWB),
                  Bf[np][0], Bf[np][1], Bf[np][2], Bf[np][3]);
#pragma unroll
        for (int mt = 0; mt < 4; mt++)
#pragma unroll
            for (int nt = 0; nt < 4; nt++)
                mma16816(acc[mt][nt], Af[mt][0], Af[mt][1], Af[mt][2], Af[mt][3],
                         Bf[nt >> 1][(nt & 1) * 2], Bf[nt >> 1][(nt & 1) * 2 + 1]);
    }
}

// ---------------- elementwise prep kernels -----------------------------------
__global__ void k_expw(const float* __restrict__ w) {
    int i = blockIdx.x * blockDim.x + threadIdx.x;   // 1M float4s
    float4 v = ((const float4*)w)[i];
    ushort4 H;
    H.x = __half_as_ushort(__float2half_rn(__expf(v.x)));
    H.y = __half_as_ushort(__float2half_rn(__expf(v.y)));
    H.z = __half_as_ushort(__float2half_rn(__expf(v.z)));
    H.w = __half_as_ushort(__float2half_rn(__expf(v.w)));
    ((ushort4*)g_ewh)[i] = H;
}

__global__ void k_xs(const float* __restrict__ x) {
    int i = blockIdx.x * blockDim.x + threadIdx.x;   // 4M float4s
    float4 v = ((const float4*)x)[i];
    ushort4 H;
    H.x = __half_as_ushort(__float2half_rn(v.x));
    H.y = __half_as_ushort(__float2half_rn(v.y));
    H.z = __half_as_ushort(__float2half_rn(v.z));
    H.w = __half_as_ushort(__float2half_rn(v.w));
    ((ushort4*)g_xs)[i] = H;
}

__global__ void k_wt(const float* __restrict__ wk, const float* __restrict__ wv) {
    __shared__ float tK[32][33], tV[32][33];
    const int bs = blockIdx.x << 5;   // k block
    const int bh = blockIdx.y << 5;   // h block
    const int tx = threadIdx.x, ty = threadIdx.y;
#pragma unroll
    for (int i = 0; i < 32; i += 8) {
        tK[ty + i][tx] = wk[(bs + ty + i) * HIDN + bh + tx];
        tV[ty + i][tx] = wv[(bs + ty + i) * HIDN + bh + tx];
    }
    __syncthreads();
#pragma unroll
    for (int i = 0; i < 32; i += 8) {
        int hl = ty + i;
        size_t oK = (size_t)(2 * (bh + hl)) * DIMK + bs + tx;
        g_wh[oK] = __float2half_rn(tK[tx][hl]);
        g_wh[oK + DIMK] = __float2half_rn(tV[tx][hl]);
    }
}

// ---------------- projection GEMM + exp + fused transpose -------------------
#define NCH_P (DIMK / 32)   // 32
#define ROWH  136           // epilogue transpose tile: halves per row (padded)
__global__ __launch_bounds__(256, 2) void k_projTC(
    const float* __restrict__ bk, const float* __restrict__ bv) {
    extern __shared__ char smem[];
    const u32 sb = smem_u32(smem);
    const int tid = threadIdx.x;
    const int wid = tid >> 5, lane = tid & 31;
    const int m0 = blockIdx.x << 7;
    const int n0 = blockIdx.y << 7;
    const int warp_m = wid >> 2, warp_n = wid & 3;
    const int m_base = warp_m * 64, n_base = warp_n * 32;

    float acc[4][4][4];
#pragma unroll
    for (int i = 0; i < 4; i++)
#pragma unroll
        for (int j = 0; j < 4; j++)
#pragma unroll
            for (int q = 0; q < 4; q++) acc[i][j][q] = 0.0f;

    const u32 aoff = (u32)(m_base + (lane & 15)) * ROWB + (u32)(lane >> 4) * 16;
    const u32 boff = (u32)(n_base + (lane & 7) + ((lane >> 4) << 3)) * ROWB +
                     (u32)((lane >> 3) & 1) * 16;

    load_stage2(sb + 0 * STAGEB, (const char*)g_xs, 2048, m0,
                (const char*)g_wh, 2048, n0, 0, tid); CP_COMMIT();
    load_stage2(sb + 1 * STAGEB, (const char*)g_xs, 2048, m0,
                (const char*)g_wh, 2048, n0, 1, tid); CP_COMMIT();
    load_stage2(sb + 2 * STAGEB, (const char*)g_xs, 2048, m0,
                (const char*)g_wh, 2048, n0, 2, tid); CP_COMMIT();

#pragma unroll 1
    for (int c = 0; c < NCH_P; c++) {
        CP_WAIT2();
        __syncthreads();
        if (c + 3 < NCH_P) {
            load_stage2(sb + (u32)((c + 3) % NSTG) * STAGEB,
                        (const char*)g_xs, 2048, m0,
                        (const char*)g_wh, 2048, n0, c + 3, tid);
            CP_COMMIT();
        }
        compute_sp(sb + (u32)(c % NSTG) * STAGEB, aoff, boff, acc);
    }

    // epilogue: bias + exp, transpose in smem, write g_zs [col][s] fp16
    __syncthreads();
    __half* st = (__half*)smem;
#pragma unroll
    for (int mt = 0; mt < 4; mt++) {
        const int sl = m_base + mt * 16 + (lane >> 2);
#pragma unroll
        for (int nt = 0; nt < 4; nt++) {
            const int nl = n_base + nt * 8 + 2 * (lane & 3);
            const int h = (n0 + nl) >> 1;
            const float bkh = bk[h], bvh = bv[h];
            float ek0 = __expf(acc[mt][nt][0] + bkh);
            float v0 = acc[mt][nt][1] + bvh;
            float ek1 = __expf(acc[mt][nt][2] + bkh);
            float v1 = acc[mt][nt][3] + bvh;
            st[nl * ROWH + sl] = __float2half_rn(ek0 * v0);
            st[(nl + 1) * ROWH + sl] = __float2half_rn(ek0);
            st[nl * ROWH + sl + 8] = __float2half_rn(ek1 * v1);
            st[(nl + 1) * ROWH + sl + 8] = __float2half_rn(ek1);
        }
    }
    __syncthreads();
    // store: 128 rows x 128 halves, coalesced 16B chunks
    const int b = m0 >> 11;
    const int s0g = m0 & 2047;
#pragma unroll
    for (int i = 0; i < 8; i++) {
        int j = tid + 256 * i;         // 0..2047
        int row = j >> 4;              // 0..127
        int ch = j & 15;               // 16B chunk within row
        uint4 v = *(const uint4*)((const char*)st + (size_t)row * (ROWH * 2) + ch * 16);
        *(uint4*)((char*)(g_zs + (size_t)(b * 256 + n0 + row) * TT + s0g) + ch * 16) = v;
    }
}

// ---------------- main GEMM + num/den epilogue ------------------------------
#define NCH_M (TT / 32)   // 64
__global__ __launch_bounds__(256, 2) void k_mainTC(float* __restrict__ out) {
    extern __shared__ char smem[];
    const u32 sb = smem_u32(smem);
    const int tid = threadIdx.x;
    const int wid = tid >> 5, lane = tid & 31;
    const int m0 = blockIdx.x << 7;
    const int n0 = blockIdx.y << 7;
    const int warp_m = wid >> 2, warp_n = wid & 3;
    const int m_base = warp_m * 64, n_base = warp_n * 32;

    float acc[4][4][4];
#pragma unroll
    for (int i = 0; i < 4; i++)
#pragma unroll
        for (int j = 0; j < 4; j++)
#pragma unroll
            for (int q = 0; q < 4; q++) acc[i][j][q] = 0.0f;

    const u32 aoff = (u32)(m_base + (lane & 15)) * ROWB + (u32)(lane >> 4) * 16;
    const u32 boff = (u32)(n_base + (lane & 7) + ((lane >> 4) << 3)) * ROWB +
                     (u32)((lane >> 3) & 1) * 16;

    load_stage2(sb + 0 * STAGEB, (const char*)g_ewh, 4096, m0,
                (const char*)g_zs, 4096, n0, 0, tid); CP_COMMIT();
    load_stage2(sb + 1 * STAGEB, (const char*)g_ewh, 4096, m0,
                (const char*)g_zs, 4096, n0, 1, tid); CP_COMMIT();
    load_stage2(sb + 2 * STAGEB, (const char*)g_ewh, 4096, m0,
                (const char*)g_zs, 4096, n0, 2, tid); CP_COMMIT();

#pragma unroll 1
    for (int c = 0; c < NCH_M; c++) {
        CP_WAIT2();
        __syncthreads();
        if (c + 3 < NCH_M) {
            load_stage2(sb + (u32)((c + 3) % NSTG) * STAGEB,
                        (const char*)g_ewh, 4096, m0,
                        (const char*)g_zs, 4096, n0, c + 3, tid);
            CP_COMMIT();
        }
        compute_sp(sb + (u32)(c % NSTG) * STAGEB, aoff, boff, acc);
    }

    const int b = n0 >> 8;
#pragma unroll
    for (int mt = 0; mt < 4; mt++) {
        const int t0 = m0 + m_base + mt * 16 + (lane >> 2);
#pragma unroll
        for (int nt = 0; nt < 4; nt++) {
            const int gcol = (n0 & 255) + n_base + nt * 8 + 2 * (lane & 3);
            const int h = gcol >> 1;
            float* o0 = out + ((size_t)(b * TT + t0)) * HIDN + h;
            o0[0] = __fdividef(acc[mt][nt][0], acc[mt][nt][1]);
            o0[8 * HIDN] = __fdividef(acc[mt][nt][2], acc[mt][nt][3]);
        }
    }
}

// ---------------- launch ----------------
extern "C" void kernel_launch(void* const* d_in, const int* in_sizes, int n_in,
                              void* d_out, int out_size) {
    const float* x  = (const float*)d_in[0];
    const float* wk = (const float*)d_in[1];
    const float* bk = (const float*)d_in[2];
    const float* wv = (const float*)d_in[3];
    const float* bv = (const float*)d_in[4];
    const float* w  = (const float*)d_in[5];
    float* out = (float*)d_out;

    cudaFuncSetAttribute(k_mainTC, cudaFuncAttributeMaxDynamicSharedMemorySize, SMEMTOT);
    cudaFuncSetAttribute(k_projTC, cudaFuncAttributeMaxDynamicSharedMemorySize, SMEMTOT);

    k_expw<<<4096, 256>>>(w);
    k_xs<<<16384, 256>>>(x);
    k_wt<<<dim3(32, 4), dim3(32, 8)>>>(wk, wv);
    k_projTC<<<dim3(128, 2), 256, SMEMTOT>>>(bk, bv);
    k_mainTC<<<dim3(16, 16), 256, SMEMTOT>>>(out);
}

// round 9
// speedup vs baseline: 3.0956x; 1.0425x over previous
#include <cuda_runtime.h>
#include <cuda_fp16.h>
#include <cstdint>

#define TT   2048
#define DIMK 1024
#define HIDN 128

typedef unsigned long long u64;
typedef unsigned int u32;

// ---------------- scratch (__device__ globals; no runtime alloc) ------------
__device__ __half g_ewh[TT * TT];        // exp(w) fp16 [t][s]
__device__ __half g_zs[TT * TT];         // zT fp16 [col][s], col=b*256+{2h:eKV,2h+1:eK}
__device__ __half g_xs[16384 * DIMK];    // x fp16 [m][k]
__device__ __half g_wh[256 * DIMK];      // W^T interleaved fp16 [n][k]

// ---------------- helpers ----------------------------------------------------
__device__ __forceinline__ u32 smem_u32(const void* p) {
    u32 a;
    asm("{ .reg .u64 t; cvta.to.shared.u64 t, %1; cvt.u32.u64 %0, t; }"
        : "=r"(a) : "l"(p));
    return a;
}
__device__ __forceinline__ void cp16(u32 s, const void* g) {
    asm volatile("cp.async.cg.shared.global [%0], [%1], 16;" :: "r"(s), "l"(g));
}
#define CP_COMMIT() asm volatile("cp.async.commit_group;" ::: "memory")
#define CP_WAIT1()  asm volatile("cp.async.wait_group 1;" ::: "memory")
#define CP_WAIT2()  asm volatile("cp.async.wait_group 2;" ::: "memory")

__device__ __forceinline__ void ldsm4(u32 addr, u32& r0, u32& r1, u32& r2, u32& r3) {
    asm volatile("ldmatrix.sync.aligned.m8n8.x4.shared.b16 {%0,%1,%2,%3}, [%4];"
                 : "=r"(r0), "=r"(r1), "=r"(r2), "=r"(r3) : "r"(addr));
}
__device__ __forceinline__ void mma16816(float* d, u32 a0, u32 a1, u32 a2, u32 a3,
                                         u32 b0, u32 b1) {
    asm volatile(
        "mma.sync.aligned.m16n8k16.row.col.f32.f16.f16.f32 "
        "{%0,%1,%2,%3}, {%4,%5,%6,%7}, {%8,%9}, {%0,%1,%2,%3};"
        : "+f"(d[0]), "+f"(d[1]), "+f"(d[2]), "+f"(d[3])
        : "r"(a0), "r"(a1), "r"(a2), "r"(a3), "r"(b0), "r"(b1));
}

// ---------------- smem layout: k-chunk 64, 2 mats (A,B), 3 stages ------------
#define ROWB   144                   // 128B data + 16B pad
#define MAT_B  (128 * ROWB)          // 18432
#define OFF_M0 0
#define OFF_M1 MAT_B
#define STAGEB (2 * MAT_B)           // 36864
#define NSTG   3
#define SMEMTOT (NSTG * STAGEB)      // 110592 -> 2 CTAs/SM

// 256-thread loader: 2048 cp16 per stage -> 8 per thread (one 128B row each).
__device__ __forceinline__ void load_stage2(
    u32 dst,
    const char* p0, size_t s0, int b0,
    const char* p1, size_t s1, int b1,
    int chunk, int tid) {
    const size_t cb = (size_t)chunk * 128;
    const int mat = tid >> 7;             // 0..1
    const int rr = tid & 127;
    const char* src = (mat ? p1 : p0) + (size_t)((mat ? b1 : b0) + rr) * (mat ? s1 : s0) + cb;
    const u32 d = dst + (u32)mat * MAT_B + (u32)rr * ROWB;
#pragma unroll
    for (int i = 0; i < 8; i++)
        cp16(d + (u32)i * 16, src + i * 16);
}

// fragment types
struct FragA { u32 a[4][4]; };
struct FragB { u32 b[2][4]; };

__device__ __forceinline__ void ldsm_phase(u32 s0, u32 aoff, u32 boff, int ks,
                                           FragA& A, FragB& B) {
    const u32 ak = aoff + (u32)ks * 32;
    const u32 bk = boff + (u32)ks * 32;
#pragma unroll
    for (int mt = 0; mt < 4; mt++)
        ldsm4(s0 + OFF_M0 + ak + (u32)mt * (16 * ROWB),
              A.a[mt][0], A.a[mt][1], A.a[mt][2], A.a[mt][3]);
#pragma unroll
    for (int np = 0; np < 2; np++)
        ldsm4(s0 + OFF_M1 + bk + (u32)np * (16 * ROWB),
              B.b[np][0], B.b[np][1], B.b[np][2], B.b[np][3]);
}
__device__ __forceinline__ void mma_phase(float (&acc)[4][4][4],
                                          const FragA& A, const FragB& B) {
#pragma unroll
    for (int mt = 0; mt < 4; mt++)
#pragma unroll
        for (int nt = 0; nt < 4; nt++)
            mma16816(acc[mt][nt], A.a[mt][0], A.a[mt][1], A.a[mt][2], A.a[mt][3],
                     B.b[nt >> 1][(nt & 1) * 2], B.b[nt >> 1][(nt & 1) * 2 + 1]);
}

// ---------------- elementwise prep kernels -----------------------------------
__global__ void k_expw(const float* __restrict__ w) {
    int i = blockIdx.x * blockDim.x + threadIdx.x;
    float4 v = ((const float4*)w)[i];
    ushort4 H;
    H.x = __half_as_ushort(__float2half_rn(__expf(v.x)));
    H.y = __half_as_ushort(__float2half_rn(__expf(v.y)));
    H.z = __half_as_ushort(__float2half_rn(__expf(v.z)));
    H.w = __half_as_ushort(__float2half_rn(__expf(v.w)));
    ((ushort4*)g_ewh)[i] = H;
}

__global__ void k_xs(const float* __restrict__ x) {
    int i = blockIdx.x * blockDim.x + threadIdx.x;
    float4 v = ((const float4*)x)[i];
    ushort4 H;
    H.x = __half_as_ushort(__float2half_rn(v.x));
    H.y = __half_as_ushort(__float2half_rn(v.y));
    H.z = __half_as_ushort(__float2half_rn(v.z));
    H.w = __half_as_ushort(__float2half_rn(v.w));
    ((ushort4*)g_xs)[i] = H;
}

__global__ void k_wt(const float* __restrict__ wk, const float* __restrict__ wv) {
    __shared__ float tK[32][33], tV[32][33];
    const int bs = blockIdx.x << 5;
    const int bh = blockIdx.y << 5;
    const int tx = threadIdx.x, ty = threadIdx.y;
#pragma unroll
    for (int i = 0; i < 32; i += 8) {
        tK[ty + i][tx] = wk[(bs + ty + i) * HIDN + bh + tx];
        tV[ty + i][tx] = wv[(bs + ty + i) * HIDN + bh + tx];
    }
    __syncthreads();
#pragma unroll
    for (int i = 0; i < 32; i += 8) {
        int hl = ty + i;
        size_t oK = (size_t)(2 * (bh + hl)) * DIMK + bs + tx;
        g_wh[oK] = __float2half_rn(tK[tx][hl]);
        g_wh[oK + DIMK] = __float2half_rn(tV[tx][hl]);
    }
}

// ---------------- projection GEMM + exp + fused transpose -------------------
#define NCH_P (DIMK / 64)   // 16
#define ROWH  136
__global__ __launch_bounds__(256, 2) void k_projTC(
    const float* __restrict__ bk, const float* __restrict__ bv) {
    extern __shared__ char smem[];
    const u32 sb = smem_u32(smem);
    const int tid = threadIdx.x;
    const int wid = tid >> 5, lane = tid & 31;
    const int m0 = blockIdx.x << 7;
    const int n0 = blockIdx.y << 7;
    const int warp_m = wid >> 2, warp_n = wid & 3;
    const int m_base = warp_m * 64, n_base = warp_n * 32;

    float acc[4][4][4];
#pragma unroll
    for (int i = 0; i < 4; i++)
#pragma unroll
        for (int j = 0; j < 4; j++)
#pragma unroll
            for (int q = 0; q < 4; q++) acc[i][j][q] = 0.0f;

    const u32 aoff = (u32)(m_base + (lane & 15)) * ROWB + (u32)(lane >> 4) * 16;
    const u32 boff = (u32)(n_base + (lane & 7) + ((lane >> 4) << 3)) * ROWB +
                     (u32)((lane >> 3) & 1) * 16;

    load_stage2(sb + 0 * STAGEB, (const char*)g_xs, 2048, m0,
                (const char*)g_wh, 2048, n0, 0, tid); CP_COMMIT();
    load_stage2(sb + 1 * STAGEB, (const char*)g_xs, 2048, m0,
                (const char*)g_wh, 2048, n0, 1, tid); CP_COMMIT();
    load_stage2(sb + 2 * STAGEB, (const char*)g_xs, 2048, m0,
                (const char*)g_wh, 2048, n0, 2, tid); CP_COMMIT();

    FragA fAa, fAb; FragB fBa, fBb;
    CP_WAIT2();
    __syncthreads();
    ldsm_phase(sb, aoff, boff, 0, fAa, fBa);

#pragma unroll 1
    for (int c = 0; c < NCH_P; c++) {
        const u32 s0 = sb + (u32)(c % NSTG) * STAGEB;
        ldsm_phase(s0, aoff, boff, 1, fAb, fBb); mma_phase(acc, fAa, fBa);
        ldsm_phase(s0, aoff, boff, 2, fAa, fBa); mma_phase(acc, fAb, fBb);
        ldsm_phase(s0, aoff, boff, 3, fAb, fBb); mma_phase(acc, fAa, fBa);
        CP_WAIT1();
        __syncthreads();
        if (c + 3 < NCH_P) {
            load_stage2(s0, (const char*)g_xs, 2048, m0,
                        (const char*)g_wh, 2048, n0, c + 3, tid);
            CP_COMMIT();
        }
        if (c + 1 < NCH_P)
            ldsm_phase(sb + (u32)((c + 1) % NSTG) * STAGEB, aoff, boff, 0, fAa, fBa);
        mma_phase(acc, fAb, fBb);
    }

    // epilogue: bias + exp, transpose in smem, write g_zs [col][s] fp16
    __syncthreads();
    __half* st = (__half*)smem;
#pragma unroll
    for (int mt = 0; mt < 4; mt++) {
        const int sl = m_base + mt * 16 + (lane >> 2);
#pragma unroll
        for (int nt = 0; nt < 4; nt++) {
            const int nl = n_base + nt * 8 + 2 * (lane & 3);
            const int h = (n0 + nl) >> 1;
            const float bkh = bk[h], bvh = bv[h];
            float ek0 = __expf(acc[mt][nt][0] + bkh);
            float v0 = acc[mt][nt][1] + bvh;
            float ek1 = __expf(acc[mt][nt][2] + bkh);
            float v1 = acc[mt][nt][3] + bvh;
            st[nl * ROWH + sl] = __float2half_rn(ek0 * v0);
            st[(nl + 1) * ROWH + sl] = __float2half_rn(ek0);
            st[nl * ROWH + sl + 8] = __float2half_rn(ek1 * v1);
            st[(nl + 1) * ROWH + sl + 8] = __float2half_rn(ek1);
        }
    }
    __syncthreads();
    const int b = m0 >> 11;
    const int s0g = m0 & 2047;
#pragma unroll
    for (int i = 0; i < 8; i++) {
        int j = tid + 256 * i;
        int row = j >> 4;
        int ch = j & 15;
        uint4 v = *(const uint4*)((const char*)st + (size_t)row * (ROWH * 2) + ch * 16);
        *(uint4*)((char*)(g_zs + (size_t)(b * 256 + n0 + row) * TT + s0g) + ch * 16) = v;
    }
}

// ---------------- main GEMM + num/den epilogue ------------------------------
#define NCH_M (TT / 64)   // 32
__global__ __launch_bounds__(256, 2) void k_mainTC(float* __restrict__ out) {
    extern __shared__ char smem[];
    const u32 sb = smem_u32(smem);
    const int tid = threadIdx.x;
    const int wid = tid >> 5, lane = tid & 31;
    const int m0 = blockIdx.x << 7;
    const int n0 = blockIdx.y << 7;
    const int warp_m = wid >> 2, warp_n = wid & 3;
    const int m_base = warp_m * 64, n_base = warp_n * 32;

    float acc[4][4][4];
#pragma unroll
    for (int i = 0; i < 4; i++)
#pragma unroll
        for (int j = 0; j < 4; j++)
#pragma unroll
            for (int q = 0; q < 4; q++) acc[i][j][q] = 0.0f;

    const u32 aoff = (u32)(m_base + (lane & 15)) * ROWB + (u32)(lane >> 4) * 16;
    const u32 boff = (u32)(n_base + (lane & 7) + ((lane >> 4) << 3)) * ROWB +
                     (u32)((lane >> 3) & 1) * 16;

    load_stage2(sb + 0 * STAGEB, (const char*)g_ewh, 4096, m0,
                (const char*)g_zs, 4096, n0, 0, tid); CP_COMMIT();
    load_stage2(sb + 1 * STAGEB, (const char*)g_ewh, 4096, m0,
                (const char*)g_zs, 4096, n0, 1, tid); CP_COMMIT();
    load_stage2(sb + 2 * STAGEB, (const char*)g_ewh, 4096, m0,
                (const char*)g_zs, 4096, n0, 2, tid); CP_COMMIT();

    FragA fAa, fAb; FragB fBa, fBb;
    CP_WAIT2();
    __syncthreads();
    ldsm_phase(sb, aoff, boff, 0, fAa, fBa);

#pragma unroll 1
    for (int c = 0; c < NCH_M; c++) {
        const u32 s0 = sb + (u32)(c % NSTG) * STAGEB;
        ldsm_phase(s0, aoff, boff, 1, fAb, fBb); mma_phase(acc, fAa, fBa);
        ldsm_phase(s0, aoff, boff, 2, fAa, fBa); mma_phase(acc, fAb, fBb);
        ldsm_phase(s0, aoff, boff, 3, fAb, fBb); mma_phase(acc, fAa, fBa);
        CP_WAIT1();
        __syncthreads();
        if (c + 3 < NCH_M) {
            load_stage2(s0, (const char*)g_ewh, 4096, m0,
                        (const char*)g_zs, 4096, n0, c + 3, tid);
            CP_COMMIT();
        }
        if (c + 1 < NCH_M)
            ldsm_phase(sb + (u32)((c + 1) % NSTG) * STAGEB, aoff, boff, 0, fAa, fBa);
        mma_phase(acc, fAb, fBb);
    }

    const int b = n0 >> 8;
#pragma unroll
    for (int mt = 0; mt < 4; mt++) {
        const int t0 = m0 + m_base + mt * 16 + (lane >> 2);
#pragma unroll
        for (int nt = 0; nt < 4; nt++) {
            const int gcol = (n0 & 255) + n_base + nt * 8 + 2 * (lane & 3);
            const int h = gcol >> 1;
            float* o0 = out + ((size_t)(b * TT + t0)) * HIDN + h;
            o0[0] = __fdividef(acc[mt][nt][0], acc[mt][nt][1]);
            o0[8 * HIDN] = __fdividef(acc[mt][nt][2], acc[mt][nt][3]);
        }
    }
}

// ---------------- launch ----------------
extern "C" void kernel_launch(void* const* d_in, const int* in_sizes, int n_in,
                              void* d_out, int out_size) {
    const float* x  = (const float*)d_in[0];
    const float* wk = (const float*)d_in[1];
    const float* bk = (const float*)d_in[2];
    const float* wv = (const float*)d_in[3];
    const float* bv = (const float*)d_in[4];
    const float* w  = (const float*)d_in[5];
    float* out = (float*)d_out;

    cudaFuncSetAttribute(k_mainTC, cudaFuncAttributeMaxDynamicSharedMemorySize, SMEMTOT);
    cudaFuncSetAttribute(k_projTC, cudaFuncAttributeMaxDynamicSharedMemorySize, SMEMTOT);

    k_expw<<<4096, 256>>>(w);
    k_xs<<<16384, 256>>>(x);
    k_wt<<<dim3(32, 4), dim3(32, 8)>>>(wk, wv);
    k_projTC<<<dim3(128, 2), 256, SMEMTOT>>>(bk, bv);
    k_mainTC<<<dim3(16, 16), 256, SMEMTOT>>>(out);
}

// round 10
// speedup vs baseline: 3.6816x; 1.1893x over previous
#include <cuda_runtime.h>
#include <cuda_fp16.h>
#include <cstdint>

#define TT   2048
#define DIMK 1024
#define HIDN 128

typedef unsigned long long u64;
typedef unsigned int u32;

// ---------------- scratch (__device__ globals; no runtime alloc) ------------
__device__ __half g_ewh[TT * TT];        // exp(w) fp16 [t][s]
__device__ __half g_zs[TT * TT];         // zT fp16 [col][s]
__device__ __half g_xs[16384 * DIMK];    // x fp16 [m][k]
__device__ __half g_wh[256 * DIMK];      // W^T interleaved fp16 [n][k]

// ---------------- helpers ----------------------------------------------------
__device__ __forceinline__ u32 smem_u32(const void* p) {
    u32 a;
    asm("{ .reg .u64 t; cvta.to.shared.u64 t, %1; cvt.u32.u64 %0, t; }"
        : "=r"(a) : "l"(p));
    return a;
}
__device__ __forceinline__ void cp16(u32 s, const void* g) {
    asm volatile("cp.async.cg.shared.global [%0], [%1], 16;" :: "r"(s), "l"(g));
}
#define CP_COMMIT() asm volatile("cp.async.commit_group;" ::: "memory")
#define CP_WAIT2()  asm volatile("cp.async.wait_group 2;" ::: "memory")

__device__ __forceinline__ void ldsm4(u32 addr, u32& r0, u32& r1, u32& r2, u32& r3) {
    asm volatile("ldmatrix.sync.aligned.m8n8.x4.shared.b16 {%0,%1,%2,%3}, [%4];"
                 : "=r"(r0), "=r"(r1), "=r"(r2), "=r"(r3) : "r"(addr));
}
__device__ __forceinline__ void mma16816(float* d, u32 a0, u32 a1, u32 a2, u32 a3,
                                         u32 b0, u32 b1) {
    asm volatile(
        "mma.sync.aligned.m16n8k16.row.col.f32.f16.f16.f32 "
        "{%0,%1,%2,%3}, {%4,%5,%6,%7}, {%8,%9}, {%0,%1,%2,%3};"
        : "+f"(d[0]), "+f"(d[1]), "+f"(d[2]), "+f"(d[3])
        : "r"(a0), "r"(a1), "r"(a2), "r"(a3), "r"(b0), "r"(b1));
}

// ---------------- smem layout: CTA 128x64, k-chunk 32, 4 stages --------------
#define ROWB   80
#define MATA_B (128 * ROWB)          // 10240 (A: 128 rows)
#define MATB_B (64 * ROWB)           // 5120  (B: 64 rows)
#define OFF_A  0
#define OFF_B  MATA_B
#define STAGEB (MATA_B + MATB_B)     // 15360
#define NSTG   4
#define SMEMTOT (NSTG * STAGEB)      // 61440 -> 3 CTAs/SM

// 256-thread loader: 768 cp16 per stage -> 3 per thread.
__device__ __forceinline__ void load_stage(
    u32 dst,
    const char* pA, size_t sA, int m0,
    const char* pB, size_t sB, int n0,
    int chunk, int tid) {
    const size_t cb = (size_t)chunk * 64;
#pragma unroll
    for (int i = 0; i < 3; i++) {
        int idx = tid + 256 * i;           // 0..767
        if (idx < 512) {                   // A: 128 rows x 4 chunks
            int rr = idx >> 2, ko = idx & 3;
            cp16(dst + OFF_A + (u32)rr * ROWB + (u32)ko * 16,
                 pA + (size_t)(m0 + rr) * sA + cb + (size_t)ko * 16);
        } else {                           // B: 64 rows x 4 chunks
            int j = idx - 512;
            int rr = j >> 2, ko = j & 3;
            cp16(dst + OFF_B + (u32)rr * ROWB + (u32)ko * 16,
                 pB + (size_t)(n0 + rr) * sB + cb + (size_t)ko * 16);
        }
    }
}

// one k=16 phase: warp tile 32x32 -> 2 A-ldsm, 2 B-ldsm, 8 MMA
__device__ __forceinline__ void phase(u32 s0, u32 aoff, u32 boff, int ks,
                                      float (&acc)[2][4][4]) {
    const u32 ak = aoff + (u32)ks * 32;
    const u32 bk = boff + (u32)ks * 32;
    u32 Af[2][4], Bf[2][4];
#pragma unroll
    for (int mt = 0; mt < 2; mt++)
        ldsm4(s0 + OFF_A + ak + (u32)mt * (16 * ROWB),
              Af[mt][0], Af[mt][1], Af[mt][2], Af[mt][3]);
#pragma unroll
    for (int np = 0; np < 2; np++)
        ldsm4(s0 + OFF_B + bk + (u32)np * (16 * ROWB),
              Bf[np][0], Bf[np][1], Bf[np][2], Bf[np][3]);
#pragma unroll
    for (int mt = 0; mt < 2; mt++)
#pragma unroll
        for (int nt = 0; nt < 4; nt++)
            mma16816(acc[mt][nt], Af[mt][0], Af[mt][1], Af[mt][2], Af[mt][3],
                     Bf[nt >> 1][(nt & 1) * 2], Bf[nt >> 1][(nt & 1) * 2 + 1]);
}

// ---------------- elementwise prep kernels -----------------------------------
__global__ void k_expw(const float* __restrict__ w) {
    int i = blockIdx.x * blockDim.x + threadIdx.x;
    float4 v = ((const float4*)w)[i];
    ushort4 H;
    H.x = __half_as_ushort(__float2half_rn(__expf(v.x)));
    H.y = __half_as_ushort(__float2half_rn(__expf(v.y)));
    H.z = __half_as_ushort(__float2half_rn(__expf(v.z)));
    H.w = __half_as_ushort(__float2half_rn(__expf(v.w)));
    ((ushort4*)g_ewh)[i] = H;
}

__global__ void k_xs(const float* __restrict__ x) {
    int i = blockIdx.x * blockDim.x + threadIdx.x;
    float4 v = ((const float4*)x)[i];
    ushort4 H;
    H.x = __half_as_ushort(__float2half_rn(v.x));
    H.y = __half_as_ushort(__float2half_rn(v.y));
    H.z = __half_as_ushort(__float2half_rn(v.z));
    H.w = __half_as_ushort(__float2half_rn(v.w));
    ((ushort4*)g_xs)[i] = H;
}

__global__ void k_wt(const float* __restrict__ wk, const float* __restrict__ wv) {
    __shared__ float tK[32][33], tV[32][33];
    const int bs = blockIdx.x << 5;
    const int bh = blockIdx.y << 5;
    const int tx = threadIdx.x, ty = threadIdx.y;
#pragma unroll
    for (int i = 0; i < 32; i += 8) {
        tK[ty + i][tx] = wk[(bs + ty + i) * HIDN + bh + tx];
        tV[ty + i][tx] = wv[(bs + ty + i) * HIDN + bh + tx];
    }
    __syncthreads();
#pragma unroll
    for (int i = 0; i < 32; i += 8) {
        int hl = ty + i;
        size_t oK = (size_t)(2 * (bh + hl)) * DIMK + bs + tx;
        g_wh[oK] = __float2half_rn(tK[tx][hl]);
        g_wh[oK + DIMK] = __float2half_rn(tV[tx][hl]);
    }
}

// ---------------- projection GEMM + exp + fused transpose -------------------
#define NCH_P (DIMK / 32)   // 32
#define ROWH  136
__global__ __launch_bounds__(256, 3) void k_projTC(
    const float* __restrict__ bk, const float* __restrict__ bv) {
    extern __shared__ char smem[];
    const u32 sb = smem_u32(smem);
    const int tid = threadIdx.x;
    const int wid = tid >> 5, lane = tid & 31;
    const int m0 = blockIdx.x << 7;    // 128 m-blocks
    const int n0 = blockIdx.y << 6;    // 4 n-blocks (64 wide)
    const int warp_m = wid >> 1, warp_n = wid & 1;
    const int m_base = warp_m * 32, n_base = warp_n * 32;

    float acc[2][4][4];
#pragma unroll
    for (int i = 0; i < 2; i++)
#pragma unroll
        for (int j = 0; j < 4; j++)
#pragma unroll
            for (int q = 0; q < 4; q++) acc[i][j][q] = 0.0f;

    const u32 aoff = (u32)(m_base + (lane & 15)) * ROWB + (u32)(lane >> 4) * 16;
    const u32 boff = (u32)(n_base + (lane & 7) + ((lane >> 4) << 3)) * ROWB +
                     (u32)((lane >> 3) & 1) * 16;

    load_stage(sb + 0 * STAGEB, (const char*)g_xs, 2048, m0,
               (const char*)g_wh, 2048, n0, 0, tid); CP_COMMIT();
    load_stage(sb + 1 * STAGEB, (const char*)g_xs, 2048, m0,
               (const char*)g_wh, 2048, n0, 1, tid); CP_COMMIT();
    load_stage(sb + 2 * STAGEB, (const char*)g_xs, 2048, m0,
               (const char*)g_wh, 2048, n0, 2, tid); CP_COMMIT();
    CP_WAIT2();
    __syncthreads();

#pragma unroll 1
    for (int c = 0; c < NCH_P; c++) {
        const u32 s0 = sb + (u32)(c & 3) * STAGEB;
        phase(s0, aoff, boff, 0, acc);
        phase(s0, aoff, boff, 1, acc);
        if (c + 3 < NCH_P)
            load_stage(sb + (u32)((c + 3) & 3) * STAGEB,
                       (const char*)g_xs, 2048, m0,
                       (const char*)g_wh, 2048, n0, c + 3, tid);
        CP_COMMIT();
        CP_WAIT2();
        __syncthreads();
    }

    // epilogue: bias + exp, transpose via smem, write g_zs [col][s] fp16
    __half* st = (__half*)smem;
#pragma unroll
    for (int mt = 0; mt < 2; mt++) {
        const int sl = m_base + mt * 16 + (lane >> 2);
#pragma unroll
        for (int nt = 0; nt < 4; nt++) {
            const int nl = n_base + nt * 8 + 2 * (lane & 3);
            const int h = (n0 + nl) >> 1;
            const float bkh = bk[h], bvh = bv[h];
            float ek0 = __expf(acc[mt][nt][0] + bkh);
            float v0 = acc[mt][nt][1] + bvh;
            float ek1 = __expf(acc[mt][nt][2] + bkh);
            float v1 = acc[mt][nt][3] + bvh;
            st[nl * ROWH + sl] = __float2half_rn(ek0 * v0);
            st[(nl + 1) * ROWH + sl] = __float2half_rn(ek0);
            st[nl * ROWH + sl + 8] = __float2half_rn(ek1 * v1);
            st[(nl + 1) * ROWH + sl + 8] = __float2half_rn(ek1);
        }
    }
    __syncthreads();
    const int b = m0 >> 11;
    const int s0g = m0 & 2047;
#pragma unroll
    for (int i = 0; i < 4; i++) {
        int j = tid + 256 * i;         // 0..1023
        int row = j >> 4;              // 0..63
        int ch = j & 15;
        uint4 v = *(const uint4*)((const char*)st + (size_t)row * (ROWH * 2) + ch * 16);
        *(uint4*)((char*)(g_zs + (size_t)(b * 256 + n0 + row) * TT + s0g) + ch * 16) = v;
    }
}

// ---------------- main GEMM + num/den epilogue ------------------------------
#define NCH_M (TT / 32)   // 64
__global__ __launch_bounds__(256, 3) void k_mainTC(float* __restrict__ out) {
    extern __shared__ char smem[];
    const u32 sb = smem_u32(smem);
    const int tid = threadIdx.x;
    const int wid = tid >> 5, lane = tid & 31;
    const int m0 = blockIdx.x << 7;   // 16 t-blocks
    const int n0 = blockIdx.y << 6;   // 32 col-blocks (64 wide)
    const int warp_m = wid >> 1, warp_n = wid & 1;
    const int m_base = warp_m * 32, n_base = warp_n * 32;

    float acc[2][4][4];
#pragma unroll
    for (int i = 0; i < 2; i++)
#pragma unroll
        for (int j = 0; j < 4; j++)
#pragma unroll
            for (int q = 0; q < 4; q++) acc[i][j][q] = 0.0f;

    const u32 aoff = (u32)(m_base + (lane & 15)) * ROWB + (u32)(lane >> 4) * 16;
    const u32 boff = (u32)(n_base + (lane & 7) + ((lane >> 4) << 3)) * ROWB +
                     (u32)((lane >> 3) & 1) * 16;

    load_stage(sb + 0 * STAGEB, (const char*)g_ewh, 4096, m0,
               (const char*)g_zs, 4096, n0, 0, tid); CP_COMMIT();
    load_stage(sb + 1 * STAGEB, (const char*)g_ewh, 4096, m0,
               (const char*)g_zs, 4096, n0, 1, tid); CP_COMMIT();
    load_stage(sb + 2 * STAGEB, (const char*)g_ewh, 4096, m0,
               (const char*)g_zs, 4096, n0, 2, tid); CP_COMMIT();
    CP_WAIT2();
    __syncthreads();

#pragma unroll 1
    for (int c = 0; c < NCH_M; c++) {
        const u32 s0 = sb + (u32)(c & 3) * STAGEB;
        phase(s0, aoff, boff, 0, acc);
        phase(s0, aoff, boff, 1, acc);
        if (c + 3 < NCH_M)
            load_stage(sb + (u32)((c + 3) & 3) * STAGEB,
                       (const char*)g_ewh, 4096, m0,
                       (const char*)g_zs, 4096, n0, c + 3, tid);
        CP_COMMIT();
        CP_WAIT2();
        __syncthreads();
    }

    const int b = n0 >> 8;
#pragma unroll
    for (int mt = 0; mt < 2; mt++) {
        const int t0 = m0 + m_base + mt * 16 + (lane >> 2);
#pragma unroll
        for (int nt = 0; nt < 4; nt++) {
            const int gcol = (n0 & 255) + n_base + nt * 8 + 2 * (lane & 3);
            const int h = gcol >> 1;
            float* o0 = out + ((size_t)(b * TT + t0)) * HIDN + h;
            o0[0] = __fdividef(acc[mt][nt][0], acc[mt][nt][1]);
            o0[8 * HIDN] = __fdividef(acc[mt][nt][2], acc[mt][nt][3]);
        }
    }
}

// ---------------- launch ----------------
extern "C" void kernel_launch(void* const* d_in, const int* in_sizes, int n_in,
                              void* d_out, int out_size) {
    const float* x  = (const float*)d_in[0];
    const float* wk = (const float*)d_in[1];
    const float* bk = (const float*)d_in[2];
    const float* wv = (const float*)d_in[3];
    const float* bv = (const float*)d_in[4];
    const float* w  = (const float*)d_in[5];
    float* out = (float*)d_out;

    cudaFuncSetAttribute(k_mainTC, cudaFuncAttributeMaxDynamicSharedMemorySize, SMEMTOT);
    cudaFuncSetAttribute(k_projTC, cudaFuncAttributeMaxDynamicSharedMemorySize, SMEMTOT);

    k_expw<<<4096, 256>>>(w);
    k_xs<<<16384, 256>>>(x);
    k_wt<<<dim3(32, 4), dim3(32, 8)>>>(wk, wv);
    k_projTC<<<dim3(128, 4), 256, SMEMTOT>>>(bk, bv);
    k_mainTC<<<dim3(16, 32), 256, SMEMTOT>>>(out);
}

// round 11
// speedup vs baseline: 4.0967x; 1.1127x over previous
#include <cuda_runtime.h>
#include <cuda_fp16.h>
#include <cstdint>

#define TT   2048
#define DIMK 1024
#define HIDN 128

typedef unsigned long long u64;
typedef unsigned int u32;

// ---------------- scratch (__device__ globals; no runtime alloc) ------------
__device__ __half g_ewh[TT * TT];        // exp(w) fp16 [t][s]
__device__ __half g_zs[TT * TT];         // zT fp16 [col][s]
__device__ __half g_xs[16384 * DIMK];    // x fp16 [m][k]
__device__ __half g_wh[256 * DIMK];      // W^T interleaved fp16 [n][k]

// ---------------- helpers ----------------------------------------------------
__device__ __forceinline__ u32 smem_u32(const void* p) {
    u32 a;
    asm("{ .reg .u64 t; cvta.to.shared.u64 t, %1; cvt.u32.u64 %0, t; }"
        : "=r"(a) : "l"(p));
    return a;
}
__device__ __forceinline__ void cp16(u32 s, const void* g) {
    asm volatile("cp.async.cg.shared.global [%0], [%1], 16;" :: "r"(s), "l"(g));
}
#define CP_COMMIT() asm volatile("cp.async.commit_group;" ::: "memory")
#define CP_WAIT2()  asm volatile("cp.async.wait_group 2;" ::: "memory")

__device__ __forceinline__ void ldsm4(u32 addr, u32& r0, u32& r1, u32& r2, u32& r3) {
    asm volatile("ldmatrix.sync.aligned.m8n8.x4.shared.b16 {%0,%1,%2,%3}, [%4];"
                 : "=r"(r0), "=r"(r1), "=r"(r2), "=r"(r3) : "r"(addr));
}
__device__ __forceinline__ void mma16816(float* d, u32 a0, u32 a1, u32 a2, u32 a3,
                                         u32 b0, u32 b1) {
    asm volatile(
        "mma.sync.aligned.m16n8k16.row.col.f32.f16.f16.f32 "
        "{%0,%1,%2,%3}, {%4,%5,%6,%7}, {%8,%9}, {%0,%1,%2,%3};"
        : "+f"(d[0]), "+f"(d[1]), "+f"(d[2]), "+f"(d[3])
        : "r"(a0), "r"(a1), "r"(a2), "r"(a3), "r"(b0), "r"(b1));
}

// ---------------- smem layout: CTA 128x128, k-chunk 32, 4 stages -------------
#define ROWB   80
#define MAT_B  (128 * ROWB)          // 10240 per operand (128 rows x 64B +pad)
#define OFF_A  0
#define OFF_B  MAT_B
#define STAGEB (2 * MAT_B)           // 20480
#define NSTG   4
#define SMEMTOT (NSTG * STAGEB)      // 81920 -> 2 CTAs/SM

// 512-thread loader: 1024 cp16 per stage -> 2 per thread.
__device__ __forceinline__ void load_stage(
    u32 dst,
    const char* pA, size_t sA, int m0,
    const char* pB, size_t sB, int n0,
    int chunk, int tid) {
    const size_t cb = (size_t)chunk * 64;
    const int rr = tid >> 2, ko = tid & 3;
    cp16(dst + OFF_A + (u32)rr * ROWB + (u32)ko * 16,
         pA + (size_t)(m0 + rr) * sA + cb + (size_t)ko * 16);
    cp16(dst + OFF_B + (u32)rr * ROWB + (u32)ko * 16,
         pB + (size_t)(n0 + rr) * sB + cb + (size_t)ko * 16);
}

// one k=16 phase: warp tile 32x32 -> 2 A-ldsm, 2 B-ldsm, 8 MMA
__device__ __forceinline__ void phase(u32 s0, u32 aoff, u32 boff, int ks,
                                      float (&acc)[2][4][4]) {
    const u32 ak = aoff + (u32)ks * 32;
    const u32 bk = boff + (u32)ks * 32;
    u32 Af[2][4], Bf[2][4];
#pragma unroll
    for (int mt = 0; mt < 2; mt++)
        ldsm4(s0 + OFF_A + ak + (u32)mt * (16 * ROWB),
              Af[mt][0], Af[mt][1], Af[mt][2], Af[mt][3]);
#pragma unroll
    for (int np = 0; np < 2; np++)
        ldsm4(s0 + OFF_B + bk + (u32)np * (16 * ROWB),
              Bf[np][0], Bf[np][1], Bf[np][2], Bf[np][3]);
#pragma unroll
    for (int mt = 0; mt < 2; mt++)
#pragma unroll
        for (int nt = 0; nt < 4; nt++)
            mma16816(acc[mt][nt], Af[mt][0], Af[mt][1], Af[mt][2], Af[mt][3],
                     Bf[nt >> 1][(nt & 1) * 2], Bf[nt >> 1][(nt & 1) * 2 + 1]);
}

// ---------------- elementwise prep kernels -----------------------------------
__global__ void k_expw(const float* __restrict__ w) {
    int i = blockIdx.x * blockDim.x + threadIdx.x;
    float4 v = ((const float4*)w)[i];
    ushort4 H;
    H.x = __half_as_ushort(__float2half_rn(__expf(v.x)));
    H.y = __half_as_ushort(__float2half_rn(__expf(v.y)));
    H.z = __half_as_ushort(__float2half_rn(__expf(v.z)));
    H.w = __half_as_ushort(__float2half_rn(__expf(v.w)));
    ((ushort4*)g_ewh)[i] = H;
}

__global__ void k_xs(const float* __restrict__ x) {
    int i = blockIdx.x * blockDim.x + threadIdx.x;
    float4 v = ((const float4*)x)[i];
    ushort4 H;
    H.x = __half_as_ushort(__float2half_rn(v.x));
    H.y = __half_as_ushort(__float2half_rn(v.y));
    H.z = __half_as_ushort(__float2half_rn(v.z));
    H.w = __half_as_ushort(__float2half_rn(v.w));
    ((ushort4*)g_xs)[i] = H;
}

__global__ void k_wt(const float* __restrict__ wk, const float* __restrict__ wv) {
    __shared__ float tK[32][33], tV[32][33];
    const int bs = blockIdx.x << 5;
    const int bh = blockIdx.y << 5;
    const int tx = threadIdx.x, ty = threadIdx.y;
#pragma unroll
    for (int i = 0; i < 32; i += 8) {
        tK[ty + i][tx] = wk[(bs + ty + i) * HIDN + bh + tx];
        tV[ty + i][tx] = wv[(bs + ty + i) * HIDN + bh + tx];
    }
    __syncthreads();
#pragma unroll
    for (int i = 0; i < 32; i += 8) {
        int hl = ty + i;
        size_t oK = (size_t)(2 * (bh + hl)) * DIMK + bs + tx;
        g_wh[oK] = __float2half_rn(tK[tx][hl]);
        g_wh[oK + DIMK] = __float2half_rn(tV[tx][hl]);
    }
}

// ---------------- projection GEMM + exp + fused transpose -------------------
#define NCH_P (DIMK / 32)   // 32
#define ROWH  136
__global__ __launch_bounds__(512, 2) void k_projTC(
    const float* __restrict__ bk, const float* __restrict__ bv) {
    extern __shared__ char smem[];
    const u32 sb = smem_u32(smem);
    const int tid = threadIdx.x;
    const int wid = tid >> 5, lane = tid & 31;
    const int m0 = blockIdx.x << 7;    // 128 m-blocks
    const int n0 = blockIdx.y << 7;    // 2 n-blocks (128 wide)
    const int warp_m = wid >> 2, warp_n = wid & 3;
    const int m_base = warp_m * 32, n_base = warp_n * 32;

    float acc[2][4][4];
#pragma unroll
    for (int i = 0; i < 2; i++)
#pragma unroll
        for (int j = 0; j < 4; j++)
#pragma unroll
            for (int q = 0; q < 4; q++) acc[i][j][q] = 0.0f;

    const u32 aoff = (u32)(m_base + (lane & 15)) * ROWB + (u32)(lane >> 4) * 16;
    const u32 boff = (u32)(n_base + (lane & 7) + ((lane >> 4) << 3)) * ROWB +
                     (u32)((lane >> 3) & 1) * 16;

    load_stage(sb + 0 * STAGEB, (const char*)g_xs, 2048, m0,
               (const char*)g_wh, 2048, n0, 0, tid); CP_COMMIT();
    load_stage(sb + 1 * STAGEB, (const char*)g_xs, 2048, m0,
               (const char*)g_wh, 2048, n0, 1, tid); CP_COMMIT();
    load_stage(sb + 2 * STAGEB, (const char*)g_xs, 2048, m0,
               (const char*)g_wh, 2048, n0, 2, tid); CP_COMMIT();
    CP_WAIT2();
    __syncthreads();

#pragma unroll 1
    for (int c = 0; c < NCH_P; c++) {
        const u32 s0 = sb + (u32)(c & 3) * STAGEB;
        phase(s0, aoff, boff, 0, acc);
        phase(s0, aoff, boff, 1, acc);
        if (c + 3 < NCH_P)
            load_stage(sb + (u32)((c + 3) & 3) * STAGEB,
                       (const char*)g_xs, 2048, m0,
                       (const char*)g_wh, 2048, n0, c + 3, tid);
        CP_COMMIT();
        CP_WAIT2();
        __syncthreads();
    }

    // epilogue: bias + exp, transpose via smem, write g_zs [col][s] fp16
    __half* st = (__half*)smem;
#pragma unroll
    for (int mt = 0; mt < 2; mt++) {
        const int sl = m_base + mt * 16 + (lane >> 2);
#pragma unroll
        for (int nt = 0; nt < 4; nt++) {
            const int nl = n_base + nt * 8 + 2 * (lane & 3);
            const int h = (n0 + nl) >> 1;
            const float bkh = bk[h], bvh = bv[h];
            float ek0 = __expf(acc[mt][nt][0] + bkh);
            float v0 = acc[mt][nt][1] + bvh;
            float ek1 = __expf(acc[mt][nt][2] + bkh);
            float v1 = acc[mt][nt][3] + bvh;
            st[nl * ROWH + sl] = __float2half_rn(ek0 * v0);
            st[(nl + 1) * ROWH + sl] = __float2half_rn(ek0);
            st[nl * ROWH + sl + 8] = __float2half_rn(ek1 * v1);
            st[(nl + 1) * ROWH + sl + 8] = __float2half_rn(ek1);
        }
    }
    __syncthreads();
    const int b = m0 >> 11;
    const int s0g = m0 & 2047;
#pragma unroll
    for (int i = 0; i < 4; i++) {
        int j = tid + 512 * i;         // 0..2047
        int row = j >> 4;              // 0..127
        int ch = j & 15;
        uint4 v = *(const uint4*)((const char*)st + (size_t)row * (ROWH * 2) + ch * 16);
        *(uint4*)((char*)(g_zs + (size_t)(b * 256 + n0 + row) * TT + s0g) + ch * 16) = v;
    }
}

// ---------------- main GEMM + num/den epilogue ------------------------------
#define NCH_M (TT / 32)   // 64
__global__ __launch_bounds__(512, 2) void k_mainTC(float* __restrict__ out) {
    extern __shared__ char smem[];
    const u32 sb = smem_u32(smem);
    const int tid = threadIdx.x;
    const int wid = tid >> 5, lane = tid & 31;
    const int m0 = blockIdx.x << 7;   // 16 t-blocks
    const int n0 = blockIdx.y << 7;   // 16 col-blocks (128 wide)
    const int warp_m = wid >> 2, warp_n = wid & 3;
    const int m_base = warp_m * 32, n_base = warp_n * 32;

    float acc[2][4][4];
#pragma unroll
    for (int i = 0; i < 2; i++)
#pragma unroll
        for (int j = 0; j < 4; j++)
#pragma unroll
            for (int q = 0; q < 4; q++) acc[i][j][q] = 0.0f;

    const u32 aoff = (u32)(m_base + (lane & 15)) * ROWB + (u32)(lane >> 4) * 16;
    const u32 boff = (u32)(n_base + (lane & 7) + ((lane >> 4) << 3)) * ROWB +
                     (u32)((lane >> 3) & 1) * 16;

    load_stage(sb + 0 * STAGEB, (const char*)g_ewh, 4096, m0,
               (const char*)g_zs, 4096, n0, 0, tid); CP_COMMIT();
    load_stage(sb + 1 * STAGEB, (const char*)g_ewh, 4096, m0,
               (const char*)g_zs, 4096, n0, 1, tid); CP_COMMIT();
    load_stage(sb + 2 * STAGEB, (const char*)g_ewh, 4096, m0,
               (const char*)g_zs, 4096, n0, 2, tid); CP_COMMIT();
    CP_WAIT2();
    __syncthreads();

#pragma unroll 1
    for (int c = 0; c < NCH_M; c++) {
        const u32 s0 = sb + (u32)(c & 3) * STAGEB;
        phase(s0, aoff, boff, 0, acc);
        phase(s0, aoff, boff, 1, acc);
        if (c + 3 < NCH_M)
            load_stage(sb + (u32)((c + 3) & 3) * STAGEB,
                       (const char*)g_ewh, 4096, m0,
                       (const char*)g_zs, 4096, n0, c + 3, tid);
        CP_COMMIT();
        CP_WAIT2();
        __syncthreads();
    }

    const int b = n0 >> 8;
#pragma unroll
    for (int mt = 0; mt < 2; mt++) {
        const int t0 = m0 + m_base + mt * 16 + (lane >> 2);
#pragma unroll
        for (int nt = 0; nt < 4; nt++) {
            const int gcol = (n0 & 255) + n_base + nt * 8 + 2 * (lane & 3);
            const int h = gcol >> 1;
            float* o0 = out + ((size_t)(b * TT + t0)) * HIDN + h;
            o0[0] = __fdividef(acc[mt][nt][0], acc[mt][nt][1]);
            o0[8 * HIDN] = __fdividef(acc[mt][nt][2], acc[mt][nt][3]);
        }
    }
}

// ---------------- launch ----------------
extern "C" void kernel_launch(void* const* d_in, const int* in_sizes, int n_in,
                              void* d_out, int out_size) {
    const float* x  = (const float*)d_in[0];
    const float* wk = (const float*)d_in[1];
    const float* bk = (const float*)d_in[2];
    const float* wv = (const float*)d_in[3];
    const float* bv = (const float*)d_in[4];
    const float* w  = (const float*)d_in[5];
    float* out = (float*)d_out;

    cudaFuncSetAttribute(k_mainTC, cudaFuncAttributeMaxDynamicSharedMemorySize, SMEMTOT);
    cudaFuncSetAttribute(k_projTC, cudaFuncAttributeMaxDynamicSharedMemorySize, SMEMTOT);

    k_expw<<<4096, 256>>>(w);
    k_xs<<<16384, 256>>>(x);
    k_wt<<<dim3(32, 4), dim3(32, 8)>>>(wk, wv);
    k_projTC<<<dim3(128, 2), 512, SMEMTOT>>>(bk, bv);
    k_mainTC<<<dim3(16, 16), 512, SMEMTOT>>>(out);
}